// round 1
// baseline (speedup 1.0000x reference)
#include <cuda_runtime.h>
#include <cuda_bf16.h>

// Problem constants
#define Bq 32
#define Tq 576
#define Cq 1024
#define Hq 16
#define Dq 64
#define Mq (Bq * Tq)          // 18432
#define N_QKV (3 * Cq)        // 3072

// Scratch (device globals; no allocation allowed)
__device__ float g_Q[(size_t)Bq * Hq * Tq * Dq];   // [B,H,T,D]
__device__ float g_K[(size_t)Bq * Hq * Tq * Dq];
__device__ float g_V[(size_t)Bq * Hq * Tq * Dq];
__device__ float g_Y[(size_t)Bq * Tq * Cq];        // [B,T,H*D] attention out

// ---------------------------------------------------------------------------
// Kernel 1: fused QKV GEMM.  A[M,C] @ W[C,3C] + bias, scatter into Q/K/V
// [B,H,T,D] layout.  128x128x16 tile, 256 threads, 8x8 per thread.
// ---------------------------------------------------------------------------
#define BM 128
#define BN 128
#define BK 16

__global__ __launch_bounds__(256) void qkv_gemm_kernel(
    const float* __restrict__ A, const float* __restrict__ W,
    const float* __restrict__ bias) {
  __shared__ float As[BK][BM + 4];
  __shared__ float Bs[BK][BN + 4];

  const int tid = threadIdx.x;
  const int m0 = blockIdx.y * BM;
  const int n0 = blockIdx.x * BN;
  const int tx = tid % 16;
  const int ty = tid / 16;

  const int arow = tid >> 2;          // 0..63
  const int acol = (tid & 3) << 2;    // 0,4,8,12
  const int brow = tid >> 5;          // 0..7
  const int bcol = (tid & 31) << 2;   // 0..124

  float acc[8][8];
#pragma unroll
  for (int i = 0; i < 8; i++)
#pragma unroll
    for (int j = 0; j < 8; j++) acc[i][j] = 0.f;

  for (int k0 = 0; k0 < Cq; k0 += BK) {
#pragma unroll
    for (int i = 0; i < 2; i++) {
      float4 v = *(const float4*)&A[(size_t)(m0 + arow + i * 64) * Cq + k0 + acol];
      As[acol + 0][arow + i * 64] = v.x;
      As[acol + 1][arow + i * 64] = v.y;
      As[acol + 2][arow + i * 64] = v.z;
      As[acol + 3][arow + i * 64] = v.w;
    }
#pragma unroll
    for (int i = 0; i < 2; i++) {
      float4 v = *(const float4*)&W[(size_t)(k0 + brow + i * 8) * N_QKV + n0 + bcol];
      *(float4*)&Bs[brow + i * 8][bcol] = v;
    }
    __syncthreads();

#pragma unroll
    for (int k = 0; k < BK; k++) {
      float4 ra0 = *(const float4*)&As[k][ty * 8];
      float4 ra1 = *(const float4*)&As[k][ty * 8 + 4];
      float4 rb0 = *(const float4*)&Bs[k][tx * 8];
      float4 rb1 = *(const float4*)&Bs[k][tx * 8 + 4];
      float ra[8] = {ra0.x, ra0.y, ra0.z, ra0.w, ra1.x, ra1.y, ra1.z, ra1.w};
      float rb[8] = {rb0.x, rb0.y, rb0.z, rb0.w, rb1.x, rb1.y, rb1.z, rb1.w};
#pragma unroll
      for (int i = 0; i < 8; i++)
#pragma unroll
        for (int j = 0; j < 8; j++) acc[i][j] = fmaf(ra[i], rb[j], acc[i][j]);
    }
    __syncthreads();
  }

  // Epilogue: bias + scatter to Q/K/V [B,H,T,D]
#pragma unroll
  for (int i = 0; i < 8; i++) {
    const int m = m0 + ty * 8 + i;
    const int b = m / Tq;
    const int t = m % Tq;
#pragma unroll
    for (int j = 0; j < 8; j++) {
      const int n = n0 + tx * 8 + j;
      const float v = acc[i][j] + bias[n];
      const int which = n >> 10;    // 0=q, 1=k, 2=v
      const int cc = n & 1023;
      const int h = cc >> 6;
      const int d = cc & 63;
      float* dst = (which == 0) ? g_Q : (which == 1) ? g_K : g_V;
      dst[((size_t)(b * Hq + h) * Tq + t) * Dq + d] = v;
    }
  }
}

// ---------------------------------------------------------------------------
// Kernel 2: causal flash attention, fp32, online softmax.
// One block = (head bh, query tile of 64).  256 threads.
// Thread t: query row qi = t/4, key-group g = t%4 (16 keys / 16 dims).
// ---------------------------------------------------------------------------
#define AT 64                 // tile size (queries & keys)
#define ATS 65                // padded smem row stride
#define ATTN_SMEM (4 * AT * ATS * 4)

__global__ __launch_bounds__(256) void flash_attn_kernel() {
  const int bh = blockIdx.x;          // 0..511
  const int qt = blockIdx.y;          // 0..8
  const int b = bh / Hq;
  const int h = bh % Hq;

  const float* Qb = g_Q + (size_t)bh * Tq * Dq;
  const float* Kb = g_K + (size_t)bh * Tq * Dq;
  const float* Vb = g_V + (size_t)bh * Tq * Dq;

  extern __shared__ float sm[];
  float* Qs = sm;                  // [64][65]
  float* Ks = Qs + AT * ATS;
  float* Vs = Ks + AT * ATS;
  float* Ps = Vs + AT * ATS;

  const int tid = threadIdx.x;
  const int qi = tid >> 2;
  const int g = tid & 3;
  const int qg = qt * AT + qi;     // global query index

  // Load Q tile
  const int q0 = qt * AT;
#pragma unroll
  for (int i = 0; i < 4; i++) {
    const int f = tid + i * 256;
    const int r = f >> 4;
    const int c = (f & 15) << 2;
    float4 v = *(const float4*)&Qb[(size_t)(q0 + r) * Dq + c];
    float* dr = &Qs[r * ATS + c];
    dr[0] = v.x; dr[1] = v.y; dr[2] = v.z; dr[3] = v.w;
  }

  float acc[16];
#pragma unroll
  for (int i = 0; i < 16; i++) acc[i] = 0.f;
  float mrow = -1e30f;
  float lrow = 0.f;

  const float scale = 1.0f / 64.0f;

  for (int kt = 0; kt <= qt; kt++) {
    const int k0 = kt * AT;
    __syncthreads();   // previous tile's K/V consumers done (and Q load on iter 0)
#pragma unroll
    for (int i = 0; i < 4; i++) {
      const int f = tid + i * 256;
      const int r = f >> 4;
      const int c = (f & 15) << 2;
      float4 vk = *(const float4*)&Kb[(size_t)(k0 + r) * Dq + c];
      float* drk = &Ks[r * ATS + c];
      drk[0] = vk.x; drk[1] = vk.y; drk[2] = vk.z; drk[3] = vk.w;
      float4 vv = *(const float4*)&Vb[(size_t)(k0 + r) * Dq + c];
      float* drv = &Vs[r * ATS + c];
      drv[0] = vv.x; drv[1] = vv.y; drv[2] = vv.z; drv[3] = vv.w;
    }
    __syncthreads();

    // Scores: s[jj] = Q[qi] . K[g*16+jj]
    float s[16];
#pragma unroll
    for (int jj = 0; jj < 16; jj++) s[jj] = 0.f;
    const float* qrow = &Qs[qi * ATS];
    const float* krow = &Ks[(g * 16) * ATS];
#pragma unroll 8
    for (int k = 0; k < Dq; k++) {
      const float qv = qrow[k];
#pragma unroll
      for (int jj = 0; jj < 16; jj++) s[jj] = fmaf(qv, krow[jj * ATS + k], s[jj]);
    }

    // Scale + causal mask
    float tmax = -1e30f;
#pragma unroll
    for (int jj = 0; jj < 16; jj++) {
      const int kg = k0 + g * 16 + jj;
      s[jj] = (kg <= qg) ? s[jj] * scale : -1e30f;
      tmax = fmaxf(tmax, s[jj]);
    }
    tmax = fmaxf(tmax, __shfl_xor_sync(0xffffffffu, tmax, 1));
    tmax = fmaxf(tmax, __shfl_xor_sync(0xffffffffu, tmax, 2));

    const float mnew = fmaxf(mrow, tmax);
    const float corr = __expf(mrow - mnew);
    float psum = 0.f;
#pragma unroll
    for (int jj = 0; jj < 16; jj++) {
      const float p = __expf(s[jj] - mnew);
      Ps[qi * ATS + g * 16 + jj] = p;
      psum += p;
    }
    psum += __shfl_xor_sync(0xffffffffu, psum, 1);
    psum += __shfl_xor_sync(0xffffffffu, psum, 2);
    lrow = lrow * corr + psum;
    mrow = mnew;
#pragma unroll
    for (int dd = 0; dd < 16; dd++) acc[dd] *= corr;

    __syncwarp();  // Ps row written by the 4 lanes of this row (same warp)

    // acc += P[qi,:] @ V[:, g*16..]
    const float* prow = &Ps[qi * ATS];
#pragma unroll 8
    for (int kj = 0; kj < AT; kj++) {
      const float p = prow[kj];
      const float* vrow = &Vs[kj * ATS + g * 16];
#pragma unroll
      for (int dd = 0; dd < 16; dd++) acc[dd] = fmaf(p, vrow[dd], acc[dd]);
    }
  }

  // Finalize: write Y in [B,T,H,D] layout
  const float inv = 1.0f / lrow;
  float* yrow = &g_Y[((size_t)(b * Tq + qg) * Hq + h) * Dq + g * 16];
#pragma unroll
  for (int dd = 0; dd < 16; dd++) yrow[dd] = acc[dd] * inv;
}

// ---------------------------------------------------------------------------
// Kernel 3: output projection.  Y[M,C] @ Wp[C,C] + bias -> out[M,C]
// ---------------------------------------------------------------------------
__global__ __launch_bounds__(256) void proj_gemm_kernel(
    const float* __restrict__ W, const float* __restrict__ bias,
    float* __restrict__ out) {
  __shared__ float As[BK][BM + 4];
  __shared__ float Bs[BK][BN + 4];

  const int tid = threadIdx.x;
  const int m0 = blockIdx.y * BM;
  const int n0 = blockIdx.x * BN;
  const int tx = tid % 16;
  const int ty = tid / 16;

  const int arow = tid >> 2;
  const int acol = (tid & 3) << 2;
  const int brow = tid >> 5;
  const int bcol = (tid & 31) << 2;

  float acc[8][8];
#pragma unroll
  for (int i = 0; i < 8; i++)
#pragma unroll
    for (int j = 0; j < 8; j++) acc[i][j] = 0.f;

  for (int k0 = 0; k0 < Cq; k0 += BK) {
#pragma unroll
    for (int i = 0; i < 2; i++) {
      float4 v = *(const float4*)&g_Y[(size_t)(m0 + arow + i * 64) * Cq + k0 + acol];
      As[acol + 0][arow + i * 64] = v.x;
      As[acol + 1][arow + i * 64] = v.y;
      As[acol + 2][arow + i * 64] = v.z;
      As[acol + 3][arow + i * 64] = v.w;
    }
#pragma unroll
    for (int i = 0; i < 2; i++) {
      float4 v = *(const float4*)&W[(size_t)(k0 + brow + i * 8) * Cq + n0 + bcol];
      *(float4*)&Bs[brow + i * 8][bcol] = v;
    }
    __syncthreads();

#pragma unroll
    for (int k = 0; k < BK; k++) {
      float4 ra0 = *(const float4*)&As[k][ty * 8];
      float4 ra1 = *(const float4*)&As[k][ty * 8 + 4];
      float4 rb0 = *(const float4*)&Bs[k][tx * 8];
      float4 rb1 = *(const float4*)&Bs[k][tx * 8 + 4];
      float ra[8] = {ra0.x, ra0.y, ra0.z, ra0.w, ra1.x, ra1.y, ra1.z, ra1.w};
      float rb[8] = {rb0.x, rb0.y, rb0.z, rb0.w, rb1.x, rb1.y, rb1.z, rb1.w};
#pragma unroll
      for (int i = 0; i < 8; i++)
#pragma unroll
        for (int j = 0; j < 8; j++) acc[i][j] = fmaf(ra[i], rb[j], acc[i][j]);
    }
    __syncthreads();
  }

#pragma unroll
  for (int i = 0; i < 8; i++) {
    const int m = m0 + ty * 8 + i;
#pragma unroll
    for (int j = 0; j < 8; j++) {
      const int n = n0 + tx * 8 + j;
      out[(size_t)m * Cq + n] = acc[i][j] + bias[n];
    }
  }
}

// ---------------------------------------------------------------------------
extern "C" void kernel_launch(void* const* d_in, const int* in_sizes, int n_in,
                              void* d_out, int out_size) {
  const float* emb    = (const float*)d_in[0];
  const float* w_qkv  = (const float*)d_in[1];
  const float* b_qkv  = (const float*)d_in[2];
  const float* w_proj = (const float*)d_in[3];
  const float* b_proj = (const float*)d_in[4];
  float* out = (float*)d_out;

  cudaFuncSetAttribute(flash_attn_kernel,
                       cudaFuncAttributeMaxDynamicSharedMemorySize, ATTN_SMEM);

  dim3 g1(N_QKV / BN, Mq / BM);
  qkv_gemm_kernel<<<g1, 256>>>(emb, w_qkv, b_qkv);

  dim3 g2(Bq * Hq, Tq / AT);
  flash_attn_kernel<<<g2, 256, ATTN_SMEM>>>();

  dim3 g3(Cq / BN, Mq / BM);
  proj_gemm_kernel<<<g3, 256>>>(w_proj, b_proj, out);
}

// round 4
// speedup vs baseline: 1.4865x; 1.4865x over previous
#include <cuda_runtime.h>
#include <cuda_bf16.h>
#include <cstdint>

// Problem constants
#define Bq 32
#define Tq 576
#define Cq 1024
#define Hq 16
#define Dq 64
#define Mq (Bq * Tq)          // 18432
#define N_QKV (3 * Cq)        // 3072

// Scratch (device globals; no allocation allowed)
__device__ float g_Q[(size_t)Bq * Hq * Tq * Dq];   // [B,H,T,D]
__device__ float g_K[(size_t)Bq * Hq * Tq * Dq];
__device__ float g_V[(size_t)Bq * Hq * Tq * Dq];
__device__ float g_Y[(size_t)Mq * Cq];             // [B,T,H*D] attention out (tf32-rounded)
__device__ float g_Atf[(size_t)Mq * Cq];           // emb rounded to tf32
__device__ float g_WqkvT[(size_t)N_QKV * Cq];      // [N=3072][K=1024], tf32-rounded
__device__ float g_WprojT[(size_t)Cq * Cq];        // [N=1024][K=1024], tf32-rounded

// ---------------------------------------------------------------------------
__device__ __forceinline__ float f2tf32(float x) {
  uint32_t r;
  asm("cvt.rna.tf32.f32 %0, %1;" : "=r"(r) : "f"(x));
  return __uint_as_float(r);
}

__device__ __forceinline__ void cp_async16(uint32_t saddr, const void* gaddr) {
  asm volatile("cp.async.cg.shared.global [%0], [%1], 16;" :: "r"(saddr), "l"(gaddr));
}
#define CP_COMMIT() asm volatile("cp.async.commit_group;" ::: "memory")
#define CP_WAIT(n)  asm volatile("cp.async.wait_group %0;" :: "n"(n) : "memory")

__device__ __forceinline__ uint32_t smem_u32(const void* p) {
  uint32_t a;
  asm("{ .reg .u64 t; cvta.to.shared.u64 t, %1; cvt.u32.u64 %0, t; }"
      : "=r"(a) : "l"(p));
  return a;
}

__device__ __forceinline__ void mma_tf32(float* c, const uint32_t* a, const uint32_t* b) {
  asm volatile(
      "mma.sync.aligned.m16n8k8.row.col.f32.tf32.tf32.f32 "
      "{%0,%1,%2,%3}, {%4,%5,%6,%7}, {%8,%9}, {%0,%1,%2,%3};"
      : "+f"(c[0]), "+f"(c[1]), "+f"(c[2]), "+f"(c[3])
      : "r"(a[0]), "r"(a[1]), "r"(a[2]), "r"(a[3]), "r"(b[0]), "r"(b[1]));
}

// ---------------------------------------------------------------------------
// emb -> tf32-rounded copy
// ---------------------------------------------------------------------------
__global__ __launch_bounds__(256) void round_tf32_kernel(const float* __restrict__ src,
                                                         float* __restrict__ dst, int n4) {
  const int i = blockIdx.x * 256 + threadIdx.x;
  if (i < n4) {
    float4 v = ((const float4*)src)[i];
    v.x = f2tf32(v.x); v.y = f2tf32(v.y); v.z = f2tf32(v.z); v.w = f2tf32(v.w);
    ((float4*)dst)[i] = v;
  }
}

// ---------------------------------------------------------------------------
// Weight transpose + tf32 rounding: dst[n][k] = tf32(src[k][n])
// ---------------------------------------------------------------------------
__global__ __launch_bounds__(256) void transpose_kernel(
    const float* __restrict__ src, float* __restrict__ dst, int R, int C) {
  __shared__ float t[32][33];
  const int c0 = blockIdx.x * 32, r0 = blockIdx.y * 32;
  const int x = threadIdx.x, y = threadIdx.y;   // 32 x 8
#pragma unroll
  for (int i = 0; i < 32; i += 8)
    t[y + i][x] = src[(size_t)(r0 + y + i) * C + c0 + x];
  __syncthreads();
#pragma unroll
  for (int i = 0; i < 32; i += 8)
    dst[(size_t)(c0 + y + i) * R + r0 + x] = f2tf32(t[x][y + i]);
}

// ---------------------------------------------------------------------------
// tf32 mma.sync GEMM: Out[M,N] = A[M,1024] @ BT[N,1024]^T + bias
// CTA 128x128x32, 256 thr, 8 warps (2m x 4n), warp 64x32, double-buffer cp.async.
// MODE 0: QKV scatter epilogue; MODE 1: plain store.
// ---------------------------------------------------------------------------
#define GKT 32
#define G_NK (Cq / GKT)           // 32
#define TS 36                     // padded row stride (floats)
#define TILE_BYTES (128 * TS * 4) // 18432
#define GK_SMEM (4 * TILE_BYTES)  // 73728

template <int MODE>
__global__ __launch_bounds__(256, 2) void tc_gemm_kernel(
    const float* __restrict__ A, const float* __restrict__ BT,
    const float* __restrict__ bias, float* __restrict__ Out) {
  extern __shared__ char smch[];
  const int tid = threadIdx.x;
  const int wid = tid >> 5;
  const int lid = tid & 31;
  const int m0 = blockIdx.y * 128;
  const int n0 = blockIdx.x * 128;
  const int warp_m = wid & 1;       // 0..1 -> 64 rows
  const int warp_n = wid >> 1;      // 0..3 -> 32 cols

  char* sA[2] = {smch, smch + 2 * TILE_BYTES};
  char* sB[2] = {smch + TILE_BYTES, smch + 3 * TILE_BYTES};

  // copy indices: 4 float4 each for A and B per thread
  const int cr = tid >> 1;                 // 0..127 (row, two threads per row)
  const int cc = (tid & 1) * 16;           // float col 0 or 16
  const float* Abase = A + (size_t)(m0 + cr) * Cq + cc;
  const float* Bbase = BT + (size_t)(n0 + cr) * Cq + cc;
  const uint32_t sAoff = (uint32_t)(cr * TS + cc) * 4;
  const uint32_t sBoff = sAoff;

  float acc[4][4][4];
#pragma unroll
  for (int i = 0; i < 4; i++)
#pragma unroll
    for (int j = 0; j < 4; j++)
#pragma unroll
      for (int q = 0; q < 4; q++) acc[i][j][q] = 0.f;

  const int g = lid >> 2, tig = lid & 3;

  // prologue: load tile 0 into buf 0
  {
    const uint32_t a0 = smem_u32(sA[0]) + sAoff;
    const uint32_t b0 = smem_u32(sB[0]) + sBoff;
#pragma unroll
    for (int v = 0; v < 4; v++) {
      cp_async16(a0 + v * 16, Abase + v * 4);
      cp_async16(b0 + v * 16, Bbase + v * 4);
    }
    CP_COMMIT();
  }

  for (int kt = 0; kt < G_NK; kt++) {
    const int buf = kt & 1;
    if (kt + 1 < G_NK) {
      const uint32_t a1 = smem_u32(sA[buf ^ 1]) + sAoff;
      const uint32_t b1 = smem_u32(sB[buf ^ 1]) + sBoff;
      const float* Ap = Abase + (size_t)(kt + 1) * GKT;
      const float* Bp = Bbase + (size_t)(kt + 1) * GKT;
#pragma unroll
      for (int v = 0; v < 4; v++) {
        cp_async16(a1 + v * 16, Ap + v * 4);
        cp_async16(b1 + v * 16, Bp + v * 4);
      }
      CP_COMMIT();
      CP_WAIT(1);
    } else {
      CP_WAIT(0);
    }
    __syncthreads();

    const uint32_t* As = (const uint32_t*)sA[buf];
    const uint32_t* Bs = (const uint32_t*)sB[buf];
    const uint32_t* Arow0 = As + (warp_m * 64 + g) * TS;
    const uint32_t* Brow0 = Bs + (warp_n * 32 + g) * TS;

#pragma unroll
    for (int ks = 0; ks < 4; ks++) {
      const int kb = ks * 8 + tig;
      uint32_t af[4][4], bf[4][2];
#pragma unroll
      for (int mt = 0; mt < 4; mt++) {
        const uint32_t* r0 = Arow0 + mt * 16 * TS;
        af[mt][0] = r0[kb];
        af[mt][1] = r0[8 * TS + kb];
        af[mt][2] = r0[kb + 4];
        af[mt][3] = r0[8 * TS + kb + 4];
      }
#pragma unroll
      for (int nt = 0; nt < 4; nt++) {
        const uint32_t* r0 = Brow0 + nt * 8 * TS;
        bf[nt][0] = r0[kb];
        bf[nt][1] = r0[kb + 4];
      }
#pragma unroll
      for (int mt = 0; mt < 4; mt++)
#pragma unroll
        for (int nt = 0; nt < 4; nt++)
          mma_tf32(acc[mt][nt], af[mt], bf[nt]);
    }
    __syncthreads();
  }

  // Epilogue
#pragma unroll
  for (int mt = 0; mt < 4; mt++) {
    const int row0 = m0 + warp_m * 64 + mt * 16 + g;
#pragma unroll
    for (int half = 0; half < 2; half++) {
      const int m = row0 + half * 8;
      const int bb = m / Tq;
      const int t = m % Tq;
#pragma unroll
      for (int nt = 0; nt < 4; nt++) {
        const int n = n0 + warp_n * 32 + nt * 8 + tig * 2;
        const float2 bv = *(const float2*)&bias[n];
        float2 o;
        o.x = acc[mt][nt][half * 2 + 0] + bv.x;
        o.y = acc[mt][nt][half * 2 + 1] + bv.y;
        if (MODE == 0) {
          const int which = n >> 10;
          const int ccn = n & 1023;
          const int h = ccn >> 6;
          const int d = ccn & 63;
          float* dst = (which == 0) ? g_Q : (which == 1) ? g_K : g_V;
          *(float2*)(dst + ((size_t)(bb * Hq + h) * Tq + t) * Dq + d) = o;
        } else {
          *(float2*)(Out + (size_t)m * Cq + n) = o;
        }
      }
    }
  }
}

// ---------------------------------------------------------------------------
// Kernel 2: causal flash attention, fp32, online softmax.
// Output rounded to tf32 (feeds proj GEMM).
// ---------------------------------------------------------------------------
#define AT 64
#define ATS 65
#define ATTN_SMEM (4 * AT * ATS * 4)

__global__ __launch_bounds__(256) void flash_attn_kernel() {
  const int bh = blockIdx.x;
  const int qt = blockIdx.y;
  const int b = bh / Hq;
  const int h = bh % Hq;

  const float* Qb = g_Q + (size_t)bh * Tq * Dq;
  const float* Kb = g_K + (size_t)bh * Tq * Dq;
  const float* Vb = g_V + (size_t)bh * Tq * Dq;

  extern __shared__ float smf[];
  float* Qs = smf;
  float* Ks = Qs + AT * ATS;
  float* Vs = Ks + AT * ATS;
  float* Ps = Vs + AT * ATS;

  const int tid = threadIdx.x;
  const int qi = tid >> 2;
  const int g = tid & 3;
  const int qg = qt * AT + qi;

  const int q0 = qt * AT;
#pragma unroll
  for (int i = 0; i < 4; i++) {
    const int f = tid + i * 256;
    const int r = f >> 4;
    const int c = (f & 15) << 2;
    float4 v = *(const float4*)&Qb[(size_t)(q0 + r) * Dq + c];
    float* dr = &Qs[r * ATS + c];
    dr[0] = v.x; dr[1] = v.y; dr[2] = v.z; dr[3] = v.w;
  }

  float acc[16];
#pragma unroll
  for (int i = 0; i < 16; i++) acc[i] = 0.f;
  float mrow = -1e30f;
  float lrow = 0.f;
  const float scale = 1.0f / 64.0f;

  for (int kt = 0; kt <= qt; kt++) {
    const int k0 = kt * AT;
    __syncthreads();
#pragma unroll
    for (int i = 0; i < 4; i++) {
      const int f = tid + i * 256;
      const int r = f >> 4;
      const int c = (f & 15) << 2;
      float4 vk = *(const float4*)&Kb[(size_t)(k0 + r) * Dq + c];
      float* drk = &Ks[r * ATS + c];
      drk[0] = vk.x; drk[1] = vk.y; drk[2] = vk.z; drk[3] = vk.w;
      float4 vv = *(const float4*)&Vb[(size_t)(k0 + r) * Dq + c];
      float* drv = &Vs[r * ATS + c];
      drv[0] = vv.x; drv[1] = vv.y; drv[2] = vv.z; drv[3] = vv.w;
    }
    __syncthreads();

    float s[16];
#pragma unroll
    for (int jj = 0; jj < 16; jj++) s[jj] = 0.f;
    const float* qrow = &Qs[qi * ATS];
    const float* krow = &Ks[(g * 16) * ATS];
#pragma unroll 8
    for (int k = 0; k < Dq; k++) {
      const float qv = qrow[k];
#pragma unroll
      for (int jj = 0; jj < 16; jj++) s[jj] = fmaf(qv, krow[jj * ATS + k], s[jj]);
    }

    float tmax = -1e30f;
#pragma unroll
    for (int jj = 0; jj < 16; jj++) {
      const int kg = k0 + g * 16 + jj;
      s[jj] = (kg <= qg) ? s[jj] * scale : -1e30f;
      tmax = fmaxf(tmax, s[jj]);
    }
    tmax = fmaxf(tmax, __shfl_xor_sync(0xffffffffu, tmax, 1));
    tmax = fmaxf(tmax, __shfl_xor_sync(0xffffffffu, tmax, 2));

    const float mnew = fmaxf(mrow, tmax);
    const float corr = __expf(mrow - mnew);
    float psum = 0.f;
#pragma unroll
    for (int jj = 0; jj < 16; jj++) {
      const float p = __expf(s[jj] - mnew);
      Ps[qi * ATS + g * 16 + jj] = p;
      psum += p;
    }
    psum += __shfl_xor_sync(0xffffffffu, psum, 1);
    psum += __shfl_xor_sync(0xffffffffu, psum, 2);
    lrow = lrow * corr + psum;
    mrow = mnew;
#pragma unroll
    for (int dd = 0; dd < 16; dd++) acc[dd] *= corr;

    __syncwarp();

    const float* prow = &Ps[qi * ATS];
#pragma unroll 8
    for (int kj = 0; kj < AT; kj++) {
      const float p = prow[kj];
      const float* vrow = &Vs[kj * ATS + g * 16];
#pragma unroll
      for (int dd = 0; dd < 16; dd++) acc[dd] = fmaf(p, vrow[dd], acc[dd]);
    }
  }

  const float inv = 1.0f / lrow;
  float* yrow = &g_Y[((size_t)(b * Tq + qg) * Hq + h) * Dq + g * 16];
#pragma unroll
  for (int dd = 0; dd < 16; dd++) yrow[dd] = f2tf32(acc[dd] * inv);
}

// ---------------------------------------------------------------------------
extern "C" void kernel_launch(void* const* d_in, const int* in_sizes, int n_in,
                              void* d_out, int out_size) {
  const float* emb    = (const float*)d_in[0];
  const float* w_qkv  = (const float*)d_in[1];
  const float* b_qkv  = (const float*)d_in[2];
  const float* w_proj = (const float*)d_in[3];
  const float* b_proj = (const float*)d_in[4];
  float* out = (float*)d_out;

  static float* p_wqkvT = nullptr;
  static float* p_wprojT = nullptr;
  static float* p_Y = nullptr;
  static float* p_Atf = nullptr;
  static bool init_done = false;
  if (!init_done) {
    cudaGetSymbolAddress((void**)&p_wqkvT, g_WqkvT);
    cudaGetSymbolAddress((void**)&p_wprojT, g_WprojT);
    cudaGetSymbolAddress((void**)&p_Y, g_Y);
    cudaGetSymbolAddress((void**)&p_Atf, g_Atf);
    cudaFuncSetAttribute(tc_gemm_kernel<0>,
                         cudaFuncAttributeMaxDynamicSharedMemorySize, GK_SMEM);
    cudaFuncSetAttribute(tc_gemm_kernel<1>,
                         cudaFuncAttributeMaxDynamicSharedMemorySize, GK_SMEM);
    cudaFuncSetAttribute(flash_attn_kernel,
                         cudaFuncAttributeMaxDynamicSharedMemorySize, ATTN_SMEM);
    init_done = true;
  }

  // tf32-round inputs (removes truncation bias in mma)
  const int n4 = Mq * Cq / 4;
  round_tf32_kernel<<<(n4 + 255) / 256, 256>>>(emb, p_Atf, n4);
  transpose_kernel<<<dim3(N_QKV / 32, Cq / 32), dim3(32, 8)>>>(w_qkv, p_wqkvT, Cq, N_QKV);
  transpose_kernel<<<dim3(Cq / 32, Cq / 32), dim3(32, 8)>>>(w_proj, p_wprojT, Cq, Cq);

  // QKV GEMM (tensor cores) with scatter epilogue
  tc_gemm_kernel<0><<<dim3(N_QKV / 128, Mq / 128), 256, GK_SMEM>>>(
      p_Atf, p_wqkvT, b_qkv, nullptr);

  // Attention
  flash_attn_kernel<<<dim3(Bq * Hq, Tq / AT), 256, ATTN_SMEM>>>();

  // Output projection (tensor cores)
  tc_gemm_kernel<1><<<dim3(Cq / 128, Mq / 128), 256, GK_SMEM>>>(
      p_Y, p_wprojT, b_proj, out);
}

// round 5
// speedup vs baseline: 3.6671x; 2.4670x over previous
#include <cuda_runtime.h>
#include <cuda_bf16.h>
#include <cstdint>

// Problem constants
#define Bq 32
#define Tq 576
#define Cq 1024
#define Hq 16
#define Dq 64
#define Mq (Bq * Tq)          // 18432
#define N_QKV (3 * Cq)        // 3072

// Scratch (device globals; no allocation allowed)
__device__ float g_Q[(size_t)Bq * Hq * Tq * Dq];   // [B,H,T,D], tf32-rounded
__device__ float g_K[(size_t)Bq * Hq * Tq * Dq];
__device__ float g_V[(size_t)Bq * Hq * Tq * Dq];
__device__ float g_Y[(size_t)Mq * Cq];             // attention out, tf32-rounded
__device__ float g_Atf[(size_t)Mq * Cq];           // emb rounded to tf32
__device__ float g_WqkvT[(size_t)N_QKV * Cq];      // [N][K], tf32-rounded
__device__ float g_WprojT[(size_t)Cq * Cq];        // [N][K], tf32-rounded

// ---------------------------------------------------------------------------
__device__ __forceinline__ float f2tf32(float x) {
  uint32_t r;
  asm("cvt.rna.tf32.f32 %0, %1;" : "=r"(r) : "f"(x));
  return __uint_as_float(r);
}

__device__ __forceinline__ void cp_async16(uint32_t saddr, const void* gaddr) {
  asm volatile("cp.async.cg.shared.global [%0], [%1], 16;" :: "r"(saddr), "l"(gaddr));
}
#define CP_COMMIT() asm volatile("cp.async.commit_group;" ::: "memory")
#define CP_WAIT(n)  asm volatile("cp.async.wait_group %0;" :: "n"(n) : "memory")

__device__ __forceinline__ uint32_t smem_u32(const void* p) {
  uint32_t a;
  asm("{ .reg .u64 t; cvta.to.shared.u64 t, %1; cvt.u32.u64 %0, t; }"
      : "=r"(a) : "l"(p));
  return a;
}

__device__ __forceinline__ void mma_tf32(float* c, const uint32_t* a, const uint32_t* b) {
  asm volatile(
      "mma.sync.aligned.m16n8k8.row.col.f32.tf32.tf32.f32 "
      "{%0,%1,%2,%3}, {%4,%5,%6,%7}, {%8,%9}, {%0,%1,%2,%3};"
      : "+f"(c[0]), "+f"(c[1]), "+f"(c[2]), "+f"(c[3])
      : "r"(a[0]), "r"(a[1]), "r"(a[2]), "r"(a[3]), "r"(b[0]), "r"(b[1]));
}

__device__ __forceinline__ void mma_tf32_2(float* c, const uint32_t* a,
                                           uint32_t b0, uint32_t b1) {
  asm volatile(
      "mma.sync.aligned.m16n8k8.row.col.f32.tf32.tf32.f32 "
      "{%0,%1,%2,%3}, {%4,%5,%6,%7}, {%8,%9}, {%0,%1,%2,%3};"
      : "+f"(c[0]), "+f"(c[1]), "+f"(c[2]), "+f"(c[3])
      : "r"(a[0]), "r"(a[1]), "r"(a[2]), "r"(a[3]), "r"(b0), "r"(b1));
}

// ---------------------------------------------------------------------------
__global__ __launch_bounds__(256) void round_tf32_kernel(const float* __restrict__ src,
                                                         float* __restrict__ dst, int n4) {
  const int i = blockIdx.x * 256 + threadIdx.x;
  if (i < n4) {
    float4 v = ((const float4*)src)[i];
    v.x = f2tf32(v.x); v.y = f2tf32(v.y); v.z = f2tf32(v.z); v.w = f2tf32(v.w);
    ((float4*)dst)[i] = v;
  }
}

__global__ __launch_bounds__(256) void transpose_kernel(
    const float* __restrict__ src, float* __restrict__ dst, int R, int C) {
  __shared__ float t[32][33];
  const int c0 = blockIdx.x * 32, r0 = blockIdx.y * 32;
  const int x = threadIdx.x, y = threadIdx.y;   // 32 x 8
#pragma unroll
  for (int i = 0; i < 32; i += 8)
    t[y + i][x] = src[(size_t)(r0 + y + i) * C + c0 + x];
  __syncthreads();
#pragma unroll
  for (int i = 0; i < 32; i += 8)
    dst[(size_t)(c0 + y + i) * R + r0 + x] = f2tf32(t[x][y + i]);
}

// ---------------------------------------------------------------------------
// tf32 mma.sync GEMM: Out[M,N] = A[M,1024] @ BT[N,1024]^T + bias
// MODE 0: QKV scatter epilogue (tf32-rounds Q/K/V); MODE 1: plain store.
// ---------------------------------------------------------------------------
#define GKT 32
#define G_NK (Cq / GKT)           // 32
#define TS 36
#define TILE_BYTES (128 * TS * 4)
#define GK_SMEM (4 * TILE_BYTES)  // 73728

template <int MODE>
__global__ __launch_bounds__(256, 2) void tc_gemm_kernel(
    const float* __restrict__ A, const float* __restrict__ BT,
    const float* __restrict__ bias, float* __restrict__ Out) {
  extern __shared__ char smch[];
  const int tid = threadIdx.x;
  const int wid = tid >> 5;
  const int lid = tid & 31;
  const int m0 = blockIdx.y * 128;
  const int n0 = blockIdx.x * 128;
  const int warp_m = wid & 1;
  const int warp_n = wid >> 1;

  char* sA[2] = {smch, smch + 2 * TILE_BYTES};
  char* sB[2] = {smch + TILE_BYTES, smch + 3 * TILE_BYTES};

  const int cr = tid >> 1;
  const int cc = (tid & 1) * 16;
  const float* Abase = A + (size_t)(m0 + cr) * Cq + cc;
  const float* Bbase = BT + (size_t)(n0 + cr) * Cq + cc;
  const uint32_t sAoff = (uint32_t)(cr * TS + cc) * 4;
  const uint32_t sBoff = sAoff;

  float acc[4][4][4];
#pragma unroll
  for (int i = 0; i < 4; i++)
#pragma unroll
    for (int j = 0; j < 4; j++)
#pragma unroll
      for (int q = 0; q < 4; q++) acc[i][j][q] = 0.f;

  const int g = lid >> 2, tig = lid & 3;

  {
    const uint32_t a0 = smem_u32(sA[0]) + sAoff;
    const uint32_t b0 = smem_u32(sB[0]) + sBoff;
#pragma unroll
    for (int v = 0; v < 4; v++) {
      cp_async16(a0 + v * 16, Abase + v * 4);
      cp_async16(b0 + v * 16, Bbase + v * 4);
    }
    CP_COMMIT();
  }

  for (int kt = 0; kt < G_NK; kt++) {
    const int buf = kt & 1;
    if (kt + 1 < G_NK) {
      const uint32_t a1 = smem_u32(sA[buf ^ 1]) + sAoff;
      const uint32_t b1 = smem_u32(sB[buf ^ 1]) + sBoff;
      const float* Ap = Abase + (size_t)(kt + 1) * GKT;
      const float* Bp = Bbase + (size_t)(kt + 1) * GKT;
#pragma unroll
      for (int v = 0; v < 4; v++) {
        cp_async16(a1 + v * 16, Ap + v * 4);
        cp_async16(b1 + v * 16, Bp + v * 4);
      }
      CP_COMMIT();
      CP_WAIT(1);
    } else {
      CP_WAIT(0);
    }
    __syncthreads();

    const uint32_t* As = (const uint32_t*)sA[buf];
    const uint32_t* Bs = (const uint32_t*)sB[buf];
    const uint32_t* Arow0 = As + (warp_m * 64 + g) * TS;
    const uint32_t* Brow0 = Bs + (warp_n * 32 + g) * TS;

#pragma unroll
    for (int ks = 0; ks < 4; ks++) {
      const int kb = ks * 8 + tig;
      uint32_t af[4][4], bf[4][2];
#pragma unroll
      for (int mt = 0; mt < 4; mt++) {
        const uint32_t* r0 = Arow0 + mt * 16 * TS;
        af[mt][0] = r0[kb];
        af[mt][1] = r0[8 * TS + kb];
        af[mt][2] = r0[kb + 4];
        af[mt][3] = r0[8 * TS + kb + 4];
      }
#pragma unroll
      for (int nt = 0; nt < 4; nt++) {
        const uint32_t* r0 = Brow0 + nt * 8 * TS;
        bf[nt][0] = r0[kb];
        bf[nt][1] = r0[kb + 4];
      }
#pragma unroll
      for (int mt = 0; mt < 4; mt++)
#pragma unroll
        for (int nt = 0; nt < 4; nt++)
          mma_tf32(acc[mt][nt], af[mt], bf[nt]);
    }
    __syncthreads();
  }

#pragma unroll
  for (int mt = 0; mt < 4; mt++) {
    const int row0 = m0 + warp_m * 64 + mt * 16 + g;
#pragma unroll
    for (int half = 0; half < 2; half++) {
      const int m = row0 + half * 8;
      const int bb = m / Tq;
      const int t = m % Tq;
#pragma unroll
      for (int nt = 0; nt < 4; nt++) {
        const int n = n0 + warp_n * 32 + nt * 8 + tig * 2;
        const float2 bv = *(const float2*)&bias[n];
        float2 o;
        o.x = acc[mt][nt][half * 2 + 0] + bv.x;
        o.y = acc[mt][nt][half * 2 + 1] + bv.y;
        if (MODE == 0) {
          o.x = f2tf32(o.x);   // unbiased tf32 for the attention mmas
          o.y = f2tf32(o.y);
          const int which = n >> 10;
          const int ccn = n & 1023;
          const int h = ccn >> 6;
          const int d = ccn & 63;
          float* dst = (which == 0) ? g_Q : (which == 1) ? g_K : g_V;
          *(float2*)(dst + ((size_t)(bb * Hq + h) * Tq + t) * Dq + d) = o;
        } else {
          *(float2*)(Out + (size_t)m * Cq + n) = o;
        }
      }
    }
  }
}

// ---------------------------------------------------------------------------
// Tensor-core causal flash attention.
// Block = (head bh, 64-query tile). 128 threads / 4 warps; warp owns 16 rows.
// S = Q@K^T and O += P@V via m16n8k8 tf32 mma. Online softmax in fragments.
// ---------------------------------------------------------------------------
#define QT 64
#define KST 68   // K smem stride: bank = 4g+tig (bijective)
#define VST 72   // V smem stride: bank = 8tig+g (bijective)
#define PST 68
#define KBUF (64 * KST)
#define VBUF (64 * VST)
#define ATTN_SMEM ((2 * KBUF + 2 * VBUF + 64 * PST) * 4)   // 89088 B

__device__ __forceinline__ void attn_prefetch(const float* Kg, const float* Vg,
                                              float* Ksb, float* Vsb, int tid) {
#pragma unroll
  for (int i = 0; i < 8; i++) {
    const int c = tid + i * 128;     // 0..1023
    const int r = c >> 4;
    const int c4 = (c & 15) * 4;
    cp_async16(smem_u32(Ksb + r * KST + c4), Kg + (size_t)r * Dq + c4);
    cp_async16(smem_u32(Vsb + r * VST + c4), Vg + (size_t)r * Dq + c4);
  }
  CP_COMMIT();
}

__global__ __launch_bounds__(128) void flash_attn_tc_kernel() {
  const int bh = blockIdx.x;          // 0..511
  const int qt = blockIdx.y;          // 0..8
  const int b = bh / Hq;
  const int h = bh % Hq;

  const float* Qb = g_Q + (size_t)bh * Tq * Dq;
  const float* Kb = g_K + (size_t)bh * Tq * Dq;
  const float* Vb = g_V + (size_t)bh * Tq * Dq;

  extern __shared__ float smf[];
  float* KsA = smf;                       // [2][64][KST]
  float* VsA = smf + 2 * KBUF;            // [2][64][VST]
  float* Ps  = smf + 2 * KBUF + 2 * VBUF; // [64][PST]

  const int tid = threadIdx.x;
  const int wid = tid >> 5;
  const int lid = tid & 31;
  const int g = lid >> 2;
  const int tig = lid & 3;
  const int q0 = qt * QT;
  const int nkt = qt + 1;

  // Prefetch K/V tile 0
  attn_prefetch(Kb, Vb, KsA, VsA, tid);

  // Stage Q tile into Ps, extract persistent A fragments
  {
#pragma unroll
    for (int i = 0; i < 8; i++) {
      const int c = tid + i * 128;
      const int r = c >> 4;
      const int c4 = (c & 15) * 4;
      const float4 v = *(const float4*)&Qb[(size_t)(q0 + r) * Dq + c4];
      float* dr = &Ps[r * PST + c4];
      dr[0] = v.x; dr[1] = v.y; dr[2] = v.z; dr[3] = v.w;
    }
  }
  __syncthreads();

  uint32_t qa[8][4];
  {
    const uint32_t* Qsm = (const uint32_t*)Ps;
    const int r0 = 16 * wid + g;
#pragma unroll
    for (int ks = 0; ks < 8; ks++) {
      const int kb = 8 * ks + tig;
      qa[ks][0] = Qsm[r0 * PST + kb];
      qa[ks][1] = Qsm[(r0 + 8) * PST + kb];
      qa[ks][2] = Qsm[r0 * PST + kb + 4];
      qa[ks][3] = Qsm[(r0 + 8) * PST + kb + 4];
    }
  }

  float o[8][4];
#pragma unroll
  for (int i = 0; i < 8; i++)
#pragma unroll
    for (int j = 0; j < 4; j++) o[i][j] = 0.f;
  float m0r = -1e30f, m1r = -1e30f, l0 = 0.f, l1 = 0.f;
  const float scale = 1.0f / 64.0f;
  const int myrow0 = 16 * wid + g;          // row within tile
  const int myrow1 = myrow0 + 8;

  for (int kt = 0; kt < nkt; kt++) {
    const int buf = kt & 1;
    __syncthreads();   // everyone done with buffer buf^1 (and Ps/Q staging)
    if (kt + 1 < nkt) {
      attn_prefetch(Kb + (size_t)(kt + 1) * 64 * Dq, Vb + (size_t)(kt + 1) * 64 * Dq,
                    KsA + (buf ^ 1) * KBUF, VsA + (buf ^ 1) * VBUF, tid);
      CP_WAIT(1);
    } else {
      CP_WAIT(0);
    }
    __syncthreads();

    // ---- S = Q @ K^T (warp rows myrow0/myrow1, 64 key cols) ----
    const uint32_t* Ksm = (const uint32_t*)(KsA + buf * KBUF);
    float s[8][4];
#pragma unroll
    for (int nt = 0; nt < 8; nt++) {
      s[nt][0] = s[nt][1] = s[nt][2] = s[nt][3] = 0.f;
      const uint32_t* kr = Ksm + (8 * nt + g) * KST;
#pragma unroll
      for (int ks = 0; ks < 8; ks++) {
        const int kb = 8 * ks + tig;
        mma_tf32_2(s[nt], qa[ks], kr[kb], kr[kb + 4]);
      }
    }

    // ---- scale + causal mask + row max ----
    const bool diag = (kt == qt);
    float mx0 = -1e30f, mx1 = -1e30f;
#pragma unroll
    for (int nt = 0; nt < 8; nt++) {
#pragma unroll
      for (int ccx = 0; ccx < 2; ccx++) {
        const int kcol = 8 * nt + 2 * tig + ccx;
        const bool ok0 = !diag || (kcol <= myrow0);
        const bool ok1 = !diag || (kcol <= myrow1);
        s[nt][ccx]     = ok0 ? s[nt][ccx] * scale     : -1e30f;
        s[nt][2 + ccx] = ok1 ? s[nt][2 + ccx] * scale : -1e30f;
        mx0 = fmaxf(mx0, s[nt][ccx]);
        mx1 = fmaxf(mx1, s[nt][2 + ccx]);
      }
    }
    mx0 = fmaxf(mx0, __shfl_xor_sync(0xffffffffu, mx0, 1));
    mx0 = fmaxf(mx0, __shfl_xor_sync(0xffffffffu, mx0, 2));
    mx1 = fmaxf(mx1, __shfl_xor_sync(0xffffffffu, mx1, 1));
    mx1 = fmaxf(mx1, __shfl_xor_sync(0xffffffffu, mx1, 2));

    const float nm0 = fmaxf(m0r, mx0);
    const float nm1 = fmaxf(m1r, mx1);
    const float c0 = __expf(m0r - nm0);
    const float c1 = __expf(m1r - nm1);

    // ---- P = exp(s - m), tf32-rounded, to smem; row sums ----
    float ps0 = 0.f, ps1 = 0.f;
#pragma unroll
    for (int nt = 0; nt < 8; nt++) {
      const float p00 = __expf(s[nt][0] - nm0);
      const float p01 = __expf(s[nt][1] - nm0);
      const float p10 = __expf(s[nt][2] - nm1);
      const float p11 = __expf(s[nt][3] - nm1);
      ps0 += p00 + p01;
      ps1 += p10 + p11;
      float2 w0 = {f2tf32(p00), f2tf32(p01)};
      float2 w1 = {f2tf32(p10), f2tf32(p11)};
      *(float2*)&Ps[myrow0 * PST + 8 * nt + 2 * tig] = w0;
      *(float2*)&Ps[myrow1 * PST + 8 * nt + 2 * tig] = w1;
    }
    ps0 += __shfl_xor_sync(0xffffffffu, ps0, 1);
    ps0 += __shfl_xor_sync(0xffffffffu, ps0, 2);
    ps1 += __shfl_xor_sync(0xffffffffu, ps1, 1);
    ps1 += __shfl_xor_sync(0xffffffffu, ps1, 2);
    l0 = l0 * c0 + ps0;
    l1 = l1 * c1 + ps1;
    m0r = nm0;
    m1r = nm1;
#pragma unroll
    for (int dt = 0; dt < 8; dt++) {
      o[dt][0] *= c0; o[dt][1] *= c0;
      o[dt][2] *= c1; o[dt][3] *= c1;
    }
    __syncwarp();   // P rows are warp-private; warp-level visibility suffices

    // ---- O += P @ V ----
    const uint32_t* Psm = (const uint32_t*)Ps;
    const uint32_t* Vsm = (const uint32_t*)(VsA + buf * VBUF);
    uint32_t pa[8][4];
#pragma unroll
    for (int ks = 0; ks < 8; ks++) {
      const int kb = 8 * ks + tig;
      pa[ks][0] = Psm[myrow0 * PST + kb];
      pa[ks][1] = Psm[myrow1 * PST + kb];
      pa[ks][2] = Psm[myrow0 * PST + kb + 4];
      pa[ks][3] = Psm[myrow1 * PST + kb + 4];
    }
#pragma unroll
    for (int dt = 0; dt < 8; dt++) {
#pragma unroll
      for (int ks = 0; ks < 8; ks++) {
        const uint32_t b0 = Vsm[(8 * ks + tig) * VST + 8 * dt + g];
        const uint32_t b1 = Vsm[(8 * ks + tig + 4) * VST + 8 * dt + g];
        mma_tf32_2(o[dt], pa[ks], b0, b1);
      }
    }
  }

  // ---- finalize: O /= l, write g_Y [B,T,H*D], tf32-rounded ----
  const float inv0 = 1.0f / l0;
  const float inv1 = 1.0f / l1;
  const int gr0 = q0 + myrow0;
  const int gr1 = q0 + myrow1;
  float* y0 = &g_Y[((size_t)(b * Tq + gr0) * Hq + h) * Dq];
  float* y1 = &g_Y[((size_t)(b * Tq + gr1) * Hq + h) * Dq];
#pragma unroll
  for (int dt = 0; dt < 8; dt++) {
    float2 w0 = {f2tf32(o[dt][0] * inv0), f2tf32(o[dt][1] * inv0)};
    float2 w1 = {f2tf32(o[dt][2] * inv1), f2tf32(o[dt][3] * inv1)};
    *(float2*)(y0 + 8 * dt + 2 * tig) = w0;
    *(float2*)(y1 + 8 * dt + 2 * tig) = w1;
  }
}

// ---------------------------------------------------------------------------
extern "C" void kernel_launch(void* const* d_in, const int* in_sizes, int n_in,
                              void* d_out, int out_size) {
  const float* emb    = (const float*)d_in[0];
  const float* w_qkv  = (const float*)d_in[1];
  const float* b_qkv  = (const float*)d_in[2];
  const float* w_proj = (const float*)d_in[3];
  const float* b_proj = (const float*)d_in[4];
  float* out = (float*)d_out;

  static float* p_wqkvT = nullptr;
  static float* p_wprojT = nullptr;
  static float* p_Y = nullptr;
  static float* p_Atf = nullptr;
  static bool init_done = false;
  if (!init_done) {
    cudaGetSymbolAddress((void**)&p_wqkvT, g_WqkvT);
    cudaGetSymbolAddress((void**)&p_wprojT, g_WprojT);
    cudaGetSymbolAddress((void**)&p_Y, g_Y);
    cudaGetSymbolAddress((void**)&p_Atf, g_Atf);
    cudaFuncSetAttribute(tc_gemm_kernel<0>,
                         cudaFuncAttributeMaxDynamicSharedMemorySize, GK_SMEM);
    cudaFuncSetAttribute(tc_gemm_kernel<1>,
                         cudaFuncAttributeMaxDynamicSharedMemorySize, GK_SMEM);
    cudaFuncSetAttribute(flash_attn_tc_kernel,
                         cudaFuncAttributeMaxDynamicSharedMemorySize, ATTN_SMEM);
    init_done = true;
  }

  const int n4 = Mq * Cq / 4;
  round_tf32_kernel<<<(n4 + 255) / 256, 256>>>(emb, p_Atf, n4);
  transpose_kernel<<<dim3(N_QKV / 32, Cq / 32), dim3(32, 8)>>>(w_qkv, p_wqkvT, Cq, N_QKV);
  transpose_kernel<<<dim3(Cq / 32, Cq / 32), dim3(32, 8)>>>(w_proj, p_wprojT, Cq, Cq);

  tc_gemm_kernel<0><<<dim3(N_QKV / 128, Mq / 128), 256, GK_SMEM>>>(
      p_Atf, p_wqkvT, b_qkv, nullptr);

  flash_attn_tc_kernel<<<dim3(Bq * Hq, Tq / QT), 128, ATTN_SMEM>>>();

  tc_gemm_kernel<1><<<dim3(Cq / 128, Mq / 128), 256, GK_SMEM>>>(
      p_Y, p_wprojT, b_proj, out);
}

// round 6
// speedup vs baseline: 4.1064x; 1.1198x over previous
#include <cuda_runtime.h>
#include <cuda_bf16.h>
#include <cstdint>

// Problem constants
#define Bq 32
#define Tq 576
#define Cq 1024
#define Hq 16
#define Dq 64
#define Mq (Bq * Tq)          // 18432
#define N_QKV (3 * Cq)        // 3072

// Scratch (device globals; no allocation allowed)
__device__ float g_Q[(size_t)Bq * Hq * Tq * Dq];   // [B,H,T,D], tf32-rounded
__device__ float g_K[(size_t)Bq * Hq * Tq * Dq];
__device__ float g_V[(size_t)Bq * Hq * Tq * Dq];
__device__ float g_Y[(size_t)Mq * Cq];             // attention out, tf32-rounded
__device__ float g_Atf[(size_t)Mq * Cq];           // emb rounded to tf32
__device__ float g_WqkvT[(size_t)N_QKV * Cq];      // [N][K], tf32-rounded
__device__ float g_WprojT[(size_t)Cq * Cq];        // [N][K], tf32-rounded

// ---------------------------------------------------------------------------
__device__ __forceinline__ float f2tf32(float x) {
  uint32_t r;
  asm("cvt.rna.tf32.f32 %0, %1;" : "=r"(r) : "f"(x));
  return __uint_as_float(r);
}

__device__ __forceinline__ void cp_async16(uint32_t saddr, const void* gaddr) {
  asm volatile("cp.async.cg.shared.global [%0], [%1], 16;" :: "r"(saddr), "l"(gaddr));
}
#define CP_COMMIT() asm volatile("cp.async.commit_group;" ::: "memory")
#define CP_WAIT(n)  asm volatile("cp.async.wait_group %0;" :: "n"(n) : "memory")

__device__ __forceinline__ uint32_t smem_u32(const void* p) {
  uint32_t a;
  asm("{ .reg .u64 t; cvta.to.shared.u64 t, %1; cvt.u32.u64 %0, t; }"
      : "=r"(a) : "l"(p));
  return a;
}

__device__ __forceinline__ void mma_tf32(float* c, const uint32_t* a, const uint32_t* b) {
  asm volatile(
      "mma.sync.aligned.m16n8k8.row.col.f32.tf32.tf32.f32 "
      "{%0,%1,%2,%3}, {%4,%5,%6,%7}, {%8,%9}, {%0,%1,%2,%3};"
      : "+f"(c[0]), "+f"(c[1]), "+f"(c[2]), "+f"(c[3])
      : "r"(a[0]), "r"(a[1]), "r"(a[2]), "r"(a[3]), "r"(b[0]), "r"(b[1]));
}

__device__ __forceinline__ void mma_tf32_2(float* c, const uint32_t* a,
                                           uint32_t b0, uint32_t b1) {
  asm volatile(
      "mma.sync.aligned.m16n8k8.row.col.f32.tf32.tf32.f32 "
      "{%0,%1,%2,%3}, {%4,%5,%6,%7}, {%8,%9}, {%0,%1,%2,%3};"
      : "+f"(c[0]), "+f"(c[1]), "+f"(c[2]), "+f"(c[3])
      : "r"(a[0]), "r"(a[1]), "r"(a[2]), "r"(a[3]), "r"(b0), "r"(b1));
}

// ---------------------------------------------------------------------------
__global__ __launch_bounds__(256) void round_tf32_kernel(const float* __restrict__ src,
                                                         float* __restrict__ dst, int n4) {
  const int i = blockIdx.x * 256 + threadIdx.x;
  if (i < n4) {
    float4 v = ((const float4*)src)[i];
    v.x = f2tf32(v.x); v.y = f2tf32(v.y); v.z = f2tf32(v.z); v.w = f2tf32(v.w);
    ((float4*)dst)[i] = v;
  }
}

__global__ __launch_bounds__(256) void transpose_kernel(
    const float* __restrict__ src, float* __restrict__ dst, int R, int C) {
  __shared__ float t[32][33];
  const int c0 = blockIdx.x * 32, r0 = blockIdx.y * 32;
  const int x = threadIdx.x, y = threadIdx.y;   // 32 x 8
#pragma unroll
  for (int i = 0; i < 32; i += 8)
    t[y + i][x] = src[(size_t)(r0 + y + i) * C + c0 + x];
  __syncthreads();
#pragma unroll
  for (int i = 0; i < 32; i += 8)
    dst[(size_t)(c0 + y + i) * R + r0 + x] = f2tf32(t[x][y + i]);
}

// ---------------------------------------------------------------------------
// tf32 mma.sync GEMM: Out[M,N] = A[M,1024] @ BT[N,1024]^T + bias
// CTA 128x128x32, 256 thr, 8 warps (2m x 4n), warp 64x32.
// 3-stage cp.async ring, ONE __syncthreads per k-tile, register-level
// fragment double buffering.
// MODE 0: QKV scatter epilogue (tf32-rounds Q/K/V); MODE 1: plain store.
// ---------------------------------------------------------------------------
#define GKT 32
#define G_NK (Cq / GKT)           // 32
#define TS 36
#define TILE_BYTES (128 * TS * 4) // 18432
#define NSTAGE 3
#define STG_BYTES (2 * TILE_BYTES)
#define GK_SMEM (NSTAGE * STG_BYTES)   // 110592

#define LOAD_FRAGS(ks_, afd, bfd) do {                                         \
  const int kb_ = (ks_) * 8 + tig;                                             \
  _Pragma("unroll")                                                            \
  for (int mt_ = 0; mt_ < 4; mt_++) {                                          \
    const uint32_t* r_ = Arow0 + mt_ * 16 * TS;                                \
    (afd)[mt_][0] = r_[kb_];                                                   \
    (afd)[mt_][1] = r_[8 * TS + kb_];                                          \
    (afd)[mt_][2] = r_[kb_ + 4];                                               \
    (afd)[mt_][3] = r_[8 * TS + kb_ + 4];                                      \
  }                                                                            \
  _Pragma("unroll")                                                            \
  for (int nt_ = 0; nt_ < 4; nt_++) {                                          \
    const uint32_t* r_ = Brow0 + nt_ * 8 * TS;                                 \
    (bfd)[nt_][0] = r_[kb_];                                                   \
    (bfd)[nt_][1] = r_[kb_ + 4];                                               \
  }                                                                            \
} while (0)

template <int MODE>
__global__ __launch_bounds__(256, 2) void tc_gemm_kernel(
    const float* __restrict__ A, const float* __restrict__ BT,
    const float* __restrict__ bias, float* __restrict__ Out) {
  extern __shared__ char smch[];
  const int tid = threadIdx.x;
  const int wid = tid >> 5;
  const int lid = tid & 31;
  const int m0 = blockIdx.y * 128;
  const int n0 = blockIdx.x * 128;
  const int warp_m = wid & 1;
  const int warp_n = wid >> 1;

  const int cr = tid >> 1;
  const int cc = (tid & 1) * 16;
  const float* Abase = A + (size_t)(m0 + cr) * Cq + cc;
  const float* Bbase = BT + (size_t)(n0 + cr) * Cq + cc;
  const uint32_t stoff = (uint32_t)(cr * TS + cc) * 4;
  const uint32_t smbase = smem_u32(smch);

  float acc[4][4][4];
#pragma unroll
  for (int i = 0; i < 4; i++)
#pragma unroll
    for (int j = 0; j < 4; j++)
#pragma unroll
      for (int q = 0; q < 4; q++) acc[i][j][q] = 0.f;

  const int g = lid >> 2, tig = lid & 3;

  // Prologue: stages 0,1
#pragma unroll
  for (int s = 0; s < NSTAGE - 1; s++) {
    const uint32_t a0 = smbase + s * STG_BYTES + stoff;
    const uint32_t b0 = a0 + TILE_BYTES;
    const float* Ap = Abase + s * GKT;
    const float* Bp = Bbase + s * GKT;
#pragma unroll
    for (int v = 0; v < 4; v++) {
      cp_async16(a0 + v * 16, Ap + v * 4);
      cp_async16(b0 + v * 16, Bp + v * 4);
    }
    CP_COMMIT();
  }

  for (int kt = 0; kt < G_NK; kt++) {
    const int cur = kt % NSTAGE;
    if (kt < G_NK - 1) { CP_WAIT(1); } else { CP_WAIT(0); }
    __syncthreads();   // stage cur visible to all; stage consumed at kt-1 free

    if (kt + 2 < G_NK) {
      const int ns = (kt + 2) % NSTAGE;
      const uint32_t a1 = smbase + ns * STG_BYTES + stoff;
      const uint32_t b1 = a1 + TILE_BYTES;
      const float* Ap = Abase + (size_t)(kt + 2) * GKT;
      const float* Bp = Bbase + (size_t)(kt + 2) * GKT;
#pragma unroll
      for (int v = 0; v < 4; v++) {
        cp_async16(a1 + v * 16, Ap + v * 4);
        cp_async16(b1 + v * 16, Bp + v * 4);
      }
      CP_COMMIT();
    }

    const uint32_t* As = (const uint32_t*)(smch + cur * STG_BYTES);
    const uint32_t* Bs = (const uint32_t*)(smch + cur * STG_BYTES + TILE_BYTES);
    const uint32_t* Arow0 = As + (warp_m * 64 + g) * TS;
    const uint32_t* Brow0 = Bs + (warp_n * 32 + g) * TS;

    uint32_t af[2][4][4], bf[2][4][2];
    LOAD_FRAGS(0, af[0], bf[0]);
#pragma unroll
    for (int ks = 0; ks < 4; ks++) {
      const int c = ks & 1;
      if (ks < 3) LOAD_FRAGS(ks + 1, af[c ^ 1], bf[c ^ 1]);
#pragma unroll
      for (int mt = 0; mt < 4; mt++)
#pragma unroll
        for (int nt = 0; nt < 4; nt++)
          mma_tf32(acc[mt][nt], af[c][mt], bf[c][nt]);
    }
  }

  __syncthreads();

#pragma unroll
  for (int mt = 0; mt < 4; mt++) {
    const int row0 = m0 + warp_m * 64 + mt * 16 + g;
#pragma unroll
    for (int half = 0; half < 2; half++) {
      const int m = row0 + half * 8;
      const int bb = m / Tq;
      const int t = m % Tq;
#pragma unroll
      for (int nt = 0; nt < 4; nt++) {
        const int n = n0 + warp_n * 32 + nt * 8 + tig * 2;
        const float2 bv = *(const float2*)&bias[n];
        float2 o;
        o.x = acc[mt][nt][half * 2 + 0] + bv.x;
        o.y = acc[mt][nt][half * 2 + 1] + bv.y;
        if (MODE == 0) {
          o.x = f2tf32(o.x);
          o.y = f2tf32(o.y);
          const int which = n >> 10;
          const int ccn = n & 1023;
          const int h = ccn >> 6;
          const int d = ccn & 63;
          float* dst = (which == 0) ? g_Q : (which == 1) ? g_K : g_V;
          *(float2*)(dst + ((size_t)(bb * Hq + h) * Tq + t) * Dq + d) = o;
        } else {
          *(float2*)(Out + (size_t)m * Cq + n) = o;
        }
      }
    }
  }
}

// ---------------------------------------------------------------------------
// Tensor-core causal flash attention (unchanged from round 5).
// ---------------------------------------------------------------------------
#define QT 64
#define KST 68
#define VST 72
#define PST 68
#define KBUF (64 * KST)
#define VBUF (64 * VST)
#define ATTN_SMEM ((2 * KBUF + 2 * VBUF + 64 * PST) * 4)   // 89088 B

__device__ __forceinline__ void attn_prefetch(const float* Kg, const float* Vg,
                                              float* Ksb, float* Vsb, int tid) {
#pragma unroll
  for (int i = 0; i < 8; i++) {
    const int c = tid + i * 128;
    const int r = c >> 4;
    const int c4 = (c & 15) * 4;
    cp_async16(smem_u32(Ksb + r * KST + c4), Kg + (size_t)r * Dq + c4);
    cp_async16(smem_u32(Vsb + r * VST + c4), Vg + (size_t)r * Dq + c4);
  }
  CP_COMMIT();
}

__global__ __launch_bounds__(128) void flash_attn_tc_kernel() {
  const int bh = blockIdx.x;
  const int qt = blockIdx.y;
  const int b = bh / Hq;
  const int h = bh % Hq;

  const float* Qb = g_Q + (size_t)bh * Tq * Dq;
  const float* Kb = g_K + (size_t)bh * Tq * Dq;
  const float* Vb = g_V + (size_t)bh * Tq * Dq;

  extern __shared__ float smf[];
  float* KsA = smf;
  float* VsA = smf + 2 * KBUF;
  float* Ps  = smf + 2 * KBUF + 2 * VBUF;

  const int tid = threadIdx.x;
  const int wid = tid >> 5;
  const int lid = tid & 31;
  const int g = lid >> 2;
  const int tig = lid & 3;
  const int q0 = qt * QT;
  const int nkt = qt + 1;

  attn_prefetch(Kb, Vb, KsA, VsA, tid);

  {
#pragma unroll
    for (int i = 0; i < 8; i++) {
      const int c = tid + i * 128;
      const int r = c >> 4;
      const int c4 = (c & 15) * 4;
      const float4 v = *(const float4*)&Qb[(size_t)(q0 + r) * Dq + c4];
      float* dr = &Ps[r * PST + c4];
      dr[0] = v.x; dr[1] = v.y; dr[2] = v.z; dr[3] = v.w;
    }
  }
  __syncthreads();

  uint32_t qa[8][4];
  {
    const uint32_t* Qsm = (const uint32_t*)Ps;
    const int r0 = 16 * wid + g;
#pragma unroll
    for (int ks = 0; ks < 8; ks++) {
      const int kb = 8 * ks + tig;
      qa[ks][0] = Qsm[r0 * PST + kb];
      qa[ks][1] = Qsm[(r0 + 8) * PST + kb];
      qa[ks][2] = Qsm[r0 * PST + kb + 4];
      qa[ks][3] = Qsm[(r0 + 8) * PST + kb + 4];
    }
  }

  float o[8][4];
#pragma unroll
  for (int i = 0; i < 8; i++)
#pragma unroll
    for (int j = 0; j < 4; j++) o[i][j] = 0.f;
  float m0r = -1e30f, m1r = -1e30f, l0 = 0.f, l1 = 0.f;
  const float scale = 1.0f / 64.0f;
  const int myrow0 = 16 * wid + g;
  const int myrow1 = myrow0 + 8;

  for (int kt = 0; kt < nkt; kt++) {
    const int buf = kt & 1;
    __syncthreads();
    if (kt + 1 < nkt) {
      attn_prefetch(Kb + (size_t)(kt + 1) * 64 * Dq, Vb + (size_t)(kt + 1) * 64 * Dq,
                    KsA + (buf ^ 1) * KBUF, VsA + (buf ^ 1) * VBUF, tid);
      CP_WAIT(1);
    } else {
      CP_WAIT(0);
    }
    __syncthreads();

    const uint32_t* Ksm = (const uint32_t*)(KsA + buf * KBUF);
    float s[8][4];
#pragma unroll
    for (int nt = 0; nt < 8; nt++) {
      s[nt][0] = s[nt][1] = s[nt][2] = s[nt][3] = 0.f;
      const uint32_t* kr = Ksm + (8 * nt + g) * KST;
#pragma unroll
      for (int ks = 0; ks < 8; ks++) {
        const int kb = 8 * ks + tig;
        mma_tf32_2(s[nt], qa[ks], kr[kb], kr[kb + 4]);
      }
    }

    const bool diag = (kt == qt);
    float mx0 = -1e30f, mx1 = -1e30f;
#pragma unroll
    for (int nt = 0; nt < 8; nt++) {
#pragma unroll
      for (int ccx = 0; ccx < 2; ccx++) {
        const int kcol = 8 * nt + 2 * tig + ccx;
        const bool ok0 = !diag || (kcol <= myrow0);
        const bool ok1 = !diag || (kcol <= myrow1);
        s[nt][ccx]     = ok0 ? s[nt][ccx] * scale     : -1e30f;
        s[nt][2 + ccx] = ok1 ? s[nt][2 + ccx] * scale : -1e30f;
        mx0 = fmaxf(mx0, s[nt][ccx]);
        mx1 = fmaxf(mx1, s[nt][2 + ccx]);
      }
    }
    mx0 = fmaxf(mx0, __shfl_xor_sync(0xffffffffu, mx0, 1));
    mx0 = fmaxf(mx0, __shfl_xor_sync(0xffffffffu, mx0, 2));
    mx1 = fmaxf(mx1, __shfl_xor_sync(0xffffffffu, mx1, 1));
    mx1 = fmaxf(mx1, __shfl_xor_sync(0xffffffffu, mx1, 2));

    const float nm0 = fmaxf(m0r, mx0);
    const float nm1 = fmaxf(m1r, mx1);
    const float c0 = __expf(m0r - nm0);
    const float c1 = __expf(m1r - nm1);

    float ps0 = 0.f, ps1 = 0.f;
#pragma unroll
    for (int nt = 0; nt < 8; nt++) {
      const float p00 = __expf(s[nt][0] - nm0);
      const float p01 = __expf(s[nt][1] - nm0);
      const float p10 = __expf(s[nt][2] - nm1);
      const float p11 = __expf(s[nt][3] - nm1);
      ps0 += p00 + p01;
      ps1 += p10 + p11;
      float2 w0 = {f2tf32(p00), f2tf32(p01)};
      float2 w1 = {f2tf32(p10), f2tf32(p11)};
      *(float2*)&Ps[myrow0 * PST + 8 * nt + 2 * tig] = w0;
      *(float2*)&Ps[myrow1 * PST + 8 * nt + 2 * tig] = w1;
    }
    ps0 += __shfl_xor_sync(0xffffffffu, ps0, 1);
    ps0 += __shfl_xor_sync(0xffffffffu, ps0, 2);
    ps1 += __shfl_xor_sync(0xffffffffu, ps1, 1);
    ps1 += __shfl_xor_sync(0xffffffffu, ps1, 2);
    l0 = l0 * c0 + ps0;
    l1 = l1 * c1 + ps1;
    m0r = nm0;
    m1r = nm1;
#pragma unroll
    for (int dt = 0; dt < 8; dt++) {
      o[dt][0] *= c0; o[dt][1] *= c0;
      o[dt][2] *= c1; o[dt][3] *= c1;
    }
    __syncwarp();

    const uint32_t* Psm = (const uint32_t*)Ps;
    const uint32_t* Vsm = (const uint32_t*)(VsA + buf * VBUF);
    uint32_t pa[8][4];
#pragma unroll
    for (int ks = 0; ks < 8; ks++) {
      const int kb = 8 * ks + tig;
      pa[ks][0] = Psm[myrow0 * PST + kb];
      pa[ks][1] = Psm[myrow1 * PST + kb];
      pa[ks][2] = Psm[myrow0 * PST + kb + 4];
      pa[ks][3] = Psm[myrow1 * PST + kb + 4];
    }
#pragma unroll
    for (int dt = 0; dt < 8; dt++) {
#pragma unroll
      for (int ks = 0; ks < 8; ks++) {
        const uint32_t b0 = Vsm[(8 * ks + tig) * VST + 8 * dt + g];
        const uint32_t b1 = Vsm[(8 * ks + tig + 4) * VST + 8 * dt + g];
        mma_tf32_2(o[dt], pa[ks], b0, b1);
      }
    }
  }

  const float inv0 = 1.0f / l0;
  const float inv1 = 1.0f / l1;
  const int gr0 = q0 + myrow0;
  const int gr1 = q0 + myrow1;
  float* y0 = &g_Y[((size_t)(b * Tq + gr0) * Hq + h) * Dq];
  float* y1 = &g_Y[((size_t)(b * Tq + gr1) * Hq + h) * Dq];
#pragma unroll
  for (int dt = 0; dt < 8; dt++) {
    float2 w0 = {f2tf32(o[dt][0] * inv0), f2tf32(o[dt][1] * inv0)};
    float2 w1 = {f2tf32(o[dt][2] * inv1), f2tf32(o[dt][3] * inv1)};
    *(float2*)(y0 + 8 * dt + 2 * tig) = w0;
    *(float2*)(y1 + 8 * dt + 2 * tig) = w1;
  }
}

// ---------------------------------------------------------------------------
extern "C" void kernel_launch(void* const* d_in, const int* in_sizes, int n_in,
                              void* d_out, int out_size) {
  const float* emb    = (const float*)d_in[0];
  const float* w_qkv  = (const float*)d_in[1];
  const float* b_qkv  = (const float*)d_in[2];
  const float* w_proj = (const float*)d_in[3];
  const float* b_proj = (const float*)d_in[4];
  float* out = (float*)d_out;

  static float* p_wqkvT = nullptr;
  static float* p_wprojT = nullptr;
  static float* p_Y = nullptr;
  static float* p_Atf = nullptr;
  static bool init_done = false;
  if (!init_done) {
    cudaGetSymbolAddress((void**)&p_wqkvT, g_WqkvT);
    cudaGetSymbolAddress((void**)&p_wprojT, g_WprojT);
    cudaGetSymbolAddress((void**)&p_Y, g_Y);
    cudaGetSymbolAddress((void**)&p_Atf, g_Atf);
    cudaFuncSetAttribute(tc_gemm_kernel<0>,
                         cudaFuncAttributeMaxDynamicSharedMemorySize, GK_SMEM);
    cudaFuncSetAttribute(tc_gemm_kernel<1>,
                         cudaFuncAttributeMaxDynamicSharedMemorySize, GK_SMEM);
    cudaFuncSetAttribute(flash_attn_tc_kernel,
                         cudaFuncAttributeMaxDynamicSharedMemorySize, ATTN_SMEM);
    init_done = true;
  }

  const int n4 = Mq * Cq / 4;
  round_tf32_kernel<<<(n4 + 255) / 256, 256>>>(emb, p_Atf, n4);
  transpose_kernel<<<dim3(N_QKV / 32, Cq / 32), dim3(32, 8)>>>(w_qkv, p_wqkvT, Cq, N_QKV);
  transpose_kernel<<<dim3(Cq / 32, Cq / 32), dim3(32, 8)>>>(w_proj, p_wprojT, Cq, Cq);

  tc_gemm_kernel<0><<<dim3(N_QKV / 128, Mq / 128), 256, GK_SMEM>>>(
      p_Atf, p_wqkvT, b_qkv, nullptr);

  flash_attn_tc_kernel<<<dim3(Bq * Hq, Tq / QT), 128, ATTN_SMEM>>>();

  tc_gemm_kernel<1><<<dim3(Cq / 128, Mq / 128), 256, GK_SMEM>>>(
      p_Y, p_wprojT, b_proj, out);
}

// round 9
// speedup vs baseline: 5.0038x; 1.2185x over previous
#include <cuda_runtime.h>
#include <cuda_bf16.h>
#include <cstdint>

// Problem constants
#define Bq 32
#define Tq 576
#define Cq 1024
#define Hq 16
#define Dq 64
#define Mq (Bq * Tq)          // 18432
#define N_QKV (3 * Cq)        // 3072

// Scratch (device globals; no allocation allowed)
__device__ float g_Q[(size_t)Bq * Hq * Tq * Dq];   // [B,H,T,D], tf32-rounded
__device__ float g_K[(size_t)Bq * Hq * Tq * Dq];
__device__ float g_V[(size_t)Bq * Hq * Tq * Dq];
__device__ float g_Y[(size_t)Mq * Cq];             // attention out, PACKED-A layout
__device__ float g_Atf[(size_t)Mq * Cq];           // emb tf32, PACKED-A layout
__device__ float g_WqkvT[(size_t)N_QKV * Cq];      // PACKED-B layout
__device__ float g_WprojT[(size_t)Cq * Cq];        // PACKED-B layout

// ---------------------------------------------------------------------------
// Fragment-packed layouts (K = 1024 fixed -> 32 k-blocks of 32).
// A[M][K]: per (mblk=m/128, kblk=k/32) a contiguous 4096-float block,
//   inner order [mt16 0..7][ks8 0..3][lid 0..31][slot 0..3]: for the
//   m16n8k8 tf32 A fragment lid = (m%8)*4 + (k%8)%4, slot = (m%16)/8 + 2*((k%8)/4).
// B[N][K]: per (nblk=n/128, kblk) 4096-float block,
//   inner order [nt8 0..15][ks8 0..3][lid][slot 0..1]: lid=(n%8)*4+(k%8)%4, slot=(k%8)/4.
// Bounds audit: A tiles = 144*32, 4096 floats each = Mq*Cq exactly; B likewise.
// ---------------------------------------------------------------------------
__device__ __forceinline__ size_t packA_idx(int m, int k) {
  const int mblk = m >> 7, kblk = k >> 5;
  const int mt = (m >> 4) & 7, ks = (k >> 3) & 3;
  const int g = m & 7, mh = (m >> 3) & 1;
  const int tig = k & 3, kh = (k >> 2) & 1;
  return ((((size_t)(mblk * 32 + kblk) * 8 + mt) * 4 + ks) * 32 + (g * 4 + tig)) * 4
         + (mh + 2 * kh);
}

__device__ __forceinline__ size_t packB_idx(int n, int k) {
  const int nblk = n >> 7, kblk = k >> 5;
  const int nt = (n >> 3) & 15, ks = (k >> 3) & 3;
  const int g = n & 7;
  const int tig = k & 3, kh = (k >> 2) & 1;
  return ((((size_t)(nblk * 32 + kblk) * 16 + nt) * 4 + ks) * 32 + (g * 4 + tig)) * 2
         + kh;
}

// ---------------------------------------------------------------------------
__device__ __forceinline__ float f2tf32(float x) {
  uint32_t r;
  asm("cvt.rna.tf32.f32 %0, %1;" : "=r"(r) : "f"(x));
  return __uint_as_float(r);
}

__device__ __forceinline__ void cp_async16(uint32_t saddr, const void* gaddr) {
  asm volatile("cp.async.cg.shared.global [%0], [%1], 16;" :: "r"(saddr), "l"(gaddr));
}
#define CP_COMMIT() asm volatile("cp.async.commit_group;" ::: "memory")
#define CP_WAIT(n)  asm volatile("cp.async.wait_group %0;" :: "n"(n) : "memory")

__device__ __forceinline__ uint32_t smem_u32(const void* p) {
  uint32_t a;
  asm("{ .reg .u64 t; cvta.to.shared.u64 t, %1; cvt.u32.u64 %0, t; }"
      : "=r"(a) : "l"(p));
  return a;
}

__device__ __forceinline__ void mma_tf32(float* c, const uint32_t* a, const uint32_t* b) {
  asm volatile(
      "mma.sync.aligned.m16n8k8.row.col.f32.tf32.tf32.f32 "
      "{%0,%1,%2,%3}, {%4,%5,%6,%7}, {%8,%9}, {%0,%1,%2,%3};"
      : "+f"(c[0]), "+f"(c[1]), "+f"(c[2]), "+f"(c[3])
      : "r"(a[0]), "r"(a[1]), "r"(a[2]), "r"(a[3]), "r"(b[0]), "r"(b[1]));
}

__device__ __forceinline__ void mma_tf32_2(float* c, const uint32_t* a,
                                           uint32_t b0, uint32_t b1) {
  asm volatile(
      "mma.sync.aligned.m16n8k8.row.col.f32.tf32.tf32.f32 "
      "{%0,%1,%2,%3}, {%4,%5,%6,%7}, {%8,%9}, {%0,%1,%2,%3};"
      : "+f"(c[0]), "+f"(c[1]), "+f"(c[2]), "+f"(c[3])
      : "r"(a[0]), "r"(a[1]), "r"(a[2]), "r"(a[3]), "r"(b0), "r"(b1));
}

// ---------------------------------------------------------------------------
// emb -> tf32-rounded, packed-A layout
// ---------------------------------------------------------------------------
__global__ __launch_bounds__(256) void round_pack_kernel(const float* __restrict__ src,
                                                         float* __restrict__ dst) {
  const int i = blockIdx.x * 256 + threadIdx.x;
  if (i < Mq * Cq / 4) {
    const int m = (i * 4) / Cq;
    const int k = (i * 4) % Cq;
    const float4 v = ((const float4*)src)[i];
    dst[packA_idx(m, k + 0)] = f2tf32(v.x);
    dst[packA_idx(m, k + 1)] = f2tf32(v.y);
    dst[packA_idx(m, k + 2)] = f2tf32(v.z);
    dst[packA_idx(m, k + 3)] = f2tf32(v.w);
  }
}

// ---------------------------------------------------------------------------
// Weight transpose + tf32 + packed-B: dst_packedB[n][k] = tf32(src[k][n])
// ---------------------------------------------------------------------------
__global__ __launch_bounds__(256) void transpose_pack_kernel(
    const float* __restrict__ src, float* __restrict__ dst, int C) {
  __shared__ float t[32][33];
  const int c0 = blockIdx.x * 32, r0 = blockIdx.y * 32;
  const int x = threadIdx.x, y = threadIdx.y;   // 32 x 8
#pragma unroll
  for (int i = 0; i < 32; i += 8)
    t[y + i][x] = src[(size_t)(r0 + y + i) * C + c0 + x];
  __syncthreads();
#pragma unroll
  for (int i = 0; i < 32; i += 8)
    dst[packB_idx(c0 + y + i, r0 + x)] = f2tf32(t[x][y + i]);
}

// ---------------------------------------------------------------------------
// tf32 mma.sync GEMM on fragment-packed operands.
// CTA 128x128x32, 256 thr, 8 warps (2m x 4n), 3-stage cp.async ring.
// MODE 0: QKV scatter epilogue (row-major Q/K/V, tf32-rounded); MODE 1: plain.
// ---------------------------------------------------------------------------
#define G_NK 32                       // k-tiles of 32
#define ATILE_F 4096                  // floats per packed (mblk,kblk) tile
#define TILE_BYTES 16384
#define NSTAGE 3
#define STG_BYTES (2 * TILE_BYTES)    // A + B
#define GK_SMEM (NSTAGE * STG_BYTES)  // 98304

#define LOAD_FRAGS(ks_, afd, bfd) do {                                         \
    _Pragma("unroll")                                                          \
    for (int mt_ = 0; mt_ < 4; mt_++)                                          \
      *(float4*)(afd)[mt_] = Afr[((warp_m * 4 + mt_) * 4 + (ks_)) * 32 + lid]; \
    _Pragma("unroll")                                                          \
    for (int nt_ = 0; nt_ < 4; nt_++)                                          \
      *(float2*)(bfd)[nt_] = Bfr[((warp_n * 4 + nt_) * 4 + (ks_)) * 32 + lid]; \
  } while (0)

template <int MODE>
__global__ __launch_bounds__(256, 2) void tc_gemm_kernel(
    const float* __restrict__ A, const float* __restrict__ BT,
    const float* __restrict__ bias, float* __restrict__ Out) {
  extern __shared__ char smch[];
  const int tid = threadIdx.x;
  const int wid = tid >> 5;
  const int lid = tid & 31;
  const int mblk = blockIdx.y;
  const int nblk = blockIdx.x;
  const int m0 = mblk * 128;
  const int n0 = nblk * 128;
  const int warp_m = wid & 1;
  const int warp_n = wid >> 1;

  const uint32_t smbase = smem_u32(smch);
  const float* Ab = A + (size_t)mblk * 32 * ATILE_F + tid * 16;
  const float* Bb = BT + (size_t)nblk * 32 * ATILE_F + tid * 16;

  float acc[4][4][4];
#pragma unroll
  for (int i = 0; i < 4; i++)
#pragma unroll
    for (int j = 0; j < 4; j++)
#pragma unroll
      for (int q = 0; q < 4; q++) acc[i][j][q] = 0.f;

  const int g = lid >> 2, tig = lid & 3;

  // Prologue: stages 0,1
#pragma unroll
  for (int s = 0; s < NSTAGE - 1; s++) {
    const uint32_t ad = smbase + s * STG_BYTES + tid * 64;
    const uint32_t bd = ad + TILE_BYTES;
    const float* Ap = Ab + (size_t)s * ATILE_F;
    const float* Bp = Bb + (size_t)s * ATILE_F;
#pragma unroll
    for (int v = 0; v < 4; v++) {
      cp_async16(ad + v * 16, Ap + v * 4);
      cp_async16(bd + v * 16, Bp + v * 4);
    }
    CP_COMMIT();
  }

  for (int kt = 0; kt < G_NK; kt++) {
    const int cur = kt % NSTAGE;
    if (kt < G_NK - 1) { CP_WAIT(1); } else { CP_WAIT(0); }
    __syncthreads();

    if (kt + 2 < G_NK) {
      const int ns = (kt + 2) % NSTAGE;
      const uint32_t ad = smbase + ns * STG_BYTES + tid * 64;
      const uint32_t bd = ad + TILE_BYTES;
      const float* Ap = Ab + (size_t)(kt + 2) * ATILE_F;
      const float* Bp = Bb + (size_t)(kt + 2) * ATILE_F;
#pragma unroll
      for (int v = 0; v < 4; v++) {
        cp_async16(ad + v * 16, Ap + v * 4);
        cp_async16(bd + v * 16, Bp + v * 4);
      }
      CP_COMMIT();
    }

    const float4* Afr = (const float4*)(smch + cur * STG_BYTES);
    const float2* Bfr = (const float2*)(smch + cur * STG_BYTES + TILE_BYTES);

    uint32_t af[2][4][4], bf[2][4][2];
    LOAD_FRAGS(0, af[0], bf[0]);
#pragma unroll
    for (int ks = 0; ks < 4; ks++) {
      const int c = ks & 1;
      if (ks < 3) LOAD_FRAGS(ks + 1, af[c ^ 1], bf[c ^ 1]);
#pragma unroll
      for (int mt = 0; mt < 4; mt++)
#pragma unroll
        for (int nt = 0; nt < 4; nt++)
          mma_tf32(acc[mt][nt], af[c][mt], bf[c][nt]);
    }
  }

  __syncthreads();

  // Epilogue (same fragment->logical mapping as rounds 4-6)
#pragma unroll
  for (int mt = 0; mt < 4; mt++) {
    const int row0 = m0 + warp_m * 64 + mt * 16 + g;
#pragma unroll
    for (int half = 0; half < 2; half++) {
      const int m = row0 + half * 8;
      const int bb = m / Tq;
      const int t = m % Tq;
#pragma unroll
      for (int nt = 0; nt < 4; nt++) {
        const int n = n0 + warp_n * 32 + nt * 8 + tig * 2;
        const float2 bv = *(const float2*)&bias[n];
        float2 o;
        o.x = acc[mt][nt][half * 2 + 0] + bv.x;
        o.y = acc[mt][nt][half * 2 + 1] + bv.y;
        if (MODE == 0) {
          o.x = f2tf32(o.x);
          o.y = f2tf32(o.y);
          const int which = n >> 10;
          const int ccn = n & 1023;
          const int h = ccn >> 6;
          const int d = ccn & 63;
          float* dst = (which == 0) ? g_Q : (which == 1) ? g_K : g_V;
          *(float2*)(dst + ((size_t)(bb * Hq + h) * Tq + t) * Dq + d) = o;
        } else {
          *(float2*)(Out + (size_t)m * Cq + n) = o;
        }
      }
    }
  }
}

// ---------------------------------------------------------------------------
// Tensor-core causal flash attention (round 5 core; epilogue writes packed-A Y).
// ---------------------------------------------------------------------------
#define QT 64
#define KST 68
#define VST 72
#define PST 68
#define KBUF (64 * KST)
#define VBUF (64 * VST)
#define ATTN_SMEM ((2 * KBUF + 2 * VBUF + 64 * PST) * 4)   // 89088 B

__device__ __forceinline__ void attn_prefetch(const float* Kg, const float* Vg,
                                              float* Ksb, float* Vsb, int tid) {
#pragma unroll
  for (int i = 0; i < 8; i++) {
    const int c = tid + i * 128;
    const int r = c >> 4;
    const int c4 = (c & 15) * 4;
    cp_async16(smem_u32(Ksb + r * KST + c4), Kg + (size_t)r * Dq + c4);
    cp_async16(smem_u32(Vsb + r * VST + c4), Vg + (size_t)r * Dq + c4);
  }
  CP_COMMIT();
}

__global__ __launch_bounds__(128) void flash_attn_tc_kernel() {
  const int bh = blockIdx.x;
  const int qt = blockIdx.y;
  const int b = bh / Hq;
  const int h = bh % Hq;

  const float* Qb = g_Q + (size_t)bh * Tq * Dq;
  const float* Kb = g_K + (size_t)bh * Tq * Dq;
  const float* Vb = g_V + (size_t)bh * Tq * Dq;

  extern __shared__ float smf[];
  float* KsA = smf;
  float* VsA = smf + 2 * KBUF;
  float* Ps  = smf + 2 * KBUF + 2 * VBUF;

  const int tid = threadIdx.x;
  const int wid = tid >> 5;
  const int lid = tid & 31;
  const int g = lid >> 2;
  const int tig = lid & 3;
  const int q0 = qt * QT;
  const int nkt = qt + 1;

  attn_prefetch(Kb, Vb, KsA, VsA, tid);

  {
#pragma unroll
    for (int i = 0; i < 8; i++) {
      const int c = tid + i * 128;
      const int r = c >> 4;
      const int c4 = (c & 15) * 4;
      const float4 v = *(const float4*)&Qb[(size_t)(q0 + r) * Dq + c4];
      float* dr = &Ps[r * PST + c4];
      dr[0] = v.x; dr[1] = v.y; dr[2] = v.z; dr[3] = v.w;
    }
  }
  __syncthreads();

  uint32_t qa[8][4];
  {
    const uint32_t* Qsm = (const uint32_t*)Ps;
    const int r0 = 16 * wid + g;
#pragma unroll
    for (int ks = 0; ks < 8; ks++) {
      const int kb = 8 * ks + tig;
      qa[ks][0] = Qsm[r0 * PST + kb];
      qa[ks][1] = Qsm[(r0 + 8) * PST + kb];
      qa[ks][2] = Qsm[r0 * PST + kb + 4];
      qa[ks][3] = Qsm[(r0 + 8) * PST + kb + 4];
    }
  }

  float o[8][4];
#pragma unroll
  for (int i = 0; i < 8; i++)
#pragma unroll
    for (int j = 0; j < 4; j++) o[i][j] = 0.f;
  float m0r = -1e30f, m1r = -1e30f, l0 = 0.f, l1 = 0.f;
  const float scale = 1.0f / 64.0f;
  const int myrow0 = 16 * wid + g;
  const int myrow1 = myrow0 + 8;

  for (int kt = 0; kt < nkt; kt++) {
    const int buf = kt & 1;
    __syncthreads();
    if (kt + 1 < nkt) {
      attn_prefetch(Kb + (size_t)(kt + 1) * 64 * Dq, Vb + (size_t)(kt + 1) * 64 * Dq,
                    KsA + (buf ^ 1) * KBUF, VsA + (buf ^ 1) * VBUF, tid);
      CP_WAIT(1);
    } else {
      CP_WAIT(0);
    }
    __syncthreads();

    const uint32_t* Ksm = (const uint32_t*)(KsA + buf * KBUF);
    float s[8][4];
#pragma unroll
    for (int nt = 0; nt < 8; nt++) {
      s[nt][0] = s[nt][1] = s[nt][2] = s[nt][3] = 0.f;
      const uint32_t* kr = Ksm + (8 * nt + g) * KST;
#pragma unroll
      for (int ks = 0; ks < 8; ks++) {
        const int kb = 8 * ks + tig;
        mma_tf32_2(s[nt], qa[ks], kr[kb], kr[kb + 4]);
      }
    }

    const bool diag = (kt == qt);
    float mx0 = -1e30f, mx1 = -1e30f;
#pragma unroll
    for (int nt = 0; nt < 8; nt++) {
#pragma unroll
      for (int ccx = 0; ccx < 2; ccx++) {
        const int kcol = 8 * nt + 2 * tig + ccx;
        const bool ok0 = !diag || (kcol <= myrow0);
        const bool ok1 = !diag || (kcol <= myrow1);
        s[nt][ccx]     = ok0 ? s[nt][ccx] * scale     : -1e30f;
        s[nt][2 + ccx] = ok1 ? s[nt][2 + ccx] * scale : -1e30f;
        mx0 = fmaxf(mx0, s[nt][ccx]);
        mx1 = fmaxf(mx1, s[nt][2 + ccx]);
      }
    }
    mx0 = fmaxf(mx0, __shfl_xor_sync(0xffffffffu, mx0, 1));
    mx0 = fmaxf(mx0, __shfl_xor_sync(0xffffffffu, mx0, 2));
    mx1 = fmaxf(mx1, __shfl_xor_sync(0xffffffffu, mx1, 1));
    mx1 = fmaxf(mx1, __shfl_xor_sync(0xffffffffu, mx1, 2));

    const float nm0 = fmaxf(m0r, mx0);
    const float nm1 = fmaxf(m1r, mx1);
    const float c0 = __expf(m0r - nm0);
    const float c1 = __expf(m1r - nm1);

    float ps0 = 0.f, ps1 = 0.f;
#pragma unroll
    for (int nt = 0; nt < 8; nt++) {
      const float p00 = __expf(s[nt][0] - nm0);
      const float p01 = __expf(s[nt][1] - nm0);
      const float p10 = __expf(s[nt][2] - nm1);
      const float p11 = __expf(s[nt][3] - nm1);
      ps0 += p00 + p01;
      ps1 += p10 + p11;
      float2 w0 = {f2tf32(p00), f2tf32(p01)};
      float2 w1 = {f2tf32(p10), f2tf32(p11)};
      *(float2*)&Ps[myrow0 * PST + 8 * nt + 2 * tig] = w0;
      *(float2*)&Ps[myrow1 * PST + 8 * nt + 2 * tig] = w1;
    }
    ps0 += __shfl_xor_sync(0xffffffffu, ps0, 1);
    ps0 += __shfl_xor_sync(0xffffffffu, ps0, 2);
    ps1 += __shfl_xor_sync(0xffffffffu, ps1, 1);
    ps1 += __shfl_xor_sync(0xffffffffu, ps1, 2);
    l0 = l0 * c0 + ps0;
    l1 = l1 * c1 + ps1;
    m0r = nm0;
    m1r = nm1;
#pragma unroll
    for (int dt = 0; dt < 8; dt++) {
      o[dt][0] *= c0; o[dt][1] *= c0;
      o[dt][2] *= c1; o[dt][3] *= c1;
    }
    __syncwarp();

    const uint32_t* Psm = (const uint32_t*)Ps;
    const uint32_t* Vsm = (const uint32_t*)(VsA + buf * VBUF);
    uint32_t pa[8][4];
#pragma unroll
    for (int ks = 0; ks < 8; ks++) {
      const int kb = 8 * ks + tig;
      pa[ks][0] = Psm[myrow0 * PST + kb];
      pa[ks][1] = Psm[myrow1 * PST + kb];
      pa[ks][2] = Psm[myrow0 * PST + kb + 4];
      pa[ks][3] = Psm[myrow1 * PST + kb + 4];
    }
#pragma unroll
    for (int dt = 0; dt < 8; dt++) {
#pragma unroll
      for (int ks = 0; ks < 8; ks++) {
        const uint32_t b0 = Vsm[(8 * ks + tig) * VST + 8 * dt + g];
        const uint32_t b1 = Vsm[(8 * ks + tig + 4) * VST + 8 * dt + g];
        mma_tf32_2(o[dt], pa[ks], b0, b1);
      }
    }
  }

  // finalize: write Y in packed-A layout (global row = b*Tq + q, col = h*64+d)
  const float inv0 = 1.0f / l0;
  const float inv1 = 1.0f / l1;
  const int mr0 = b * Tq + q0 + myrow0;
  const int mr1 = b * Tq + q0 + myrow1;
#pragma unroll
  for (int dt = 0; dt < 8; dt++) {
    const int kc = h * 64 + 8 * dt + 2 * tig;
    g_Y[packA_idx(mr0, kc)]     = f2tf32(o[dt][0] * inv0);
    g_Y[packA_idx(mr0, kc + 1)] = f2tf32(o[dt][1] * inv0);
    g_Y[packA_idx(mr1, kc)]     = f2tf32(o[dt][2] * inv1);
    g_Y[packA_idx(mr1, kc + 1)] = f2tf32(o[dt][3] * inv1);
  }
}

// ---------------------------------------------------------------------------
extern "C" void kernel_launch(void* const* d_in, const int* in_sizes, int n_in,
                              void* d_out, int out_size) {
  const float* emb    = (const float*)d_in[0];
  const float* w_qkv  = (const float*)d_in[1];
  const float* b_qkv  = (const float*)d_in[2];
  const float* w_proj = (const float*)d_in[3];
  const float* b_proj = (const float*)d_in[4];
  float* out = (float*)d_out;

  static float* p_wqkvT = nullptr;
  static float* p_wprojT = nullptr;
  static float* p_Y = nullptr;
  static float* p_Atf = nullptr;
  static bool init_done = false;
  if (!init_done) {
    cudaGetSymbolAddress((void**)&p_wqkvT, g_WqkvT);
    cudaGetSymbolAddress((void**)&p_wprojT, g_WprojT);
    cudaGetSymbolAddress((void**)&p_Y, g_Y);
    cudaGetSymbolAddress((void**)&p_Atf, g_Atf);
    cudaFuncSetAttribute(tc_gemm_kernel<0>,
                         cudaFuncAttributeMaxDynamicSharedMemorySize, GK_SMEM);
    cudaFuncSetAttribute(tc_gemm_kernel<1>,
                         cudaFuncAttributeMaxDynamicSharedMemorySize, GK_SMEM);
    cudaFuncSetAttribute(flash_attn_tc_kernel,
                         cudaFuncAttributeMaxDynamicSharedMemorySize, ATTN_SMEM);
    init_done = true;
  }

  round_pack_kernel<<<Mq * Cq / 4 / 256, 256>>>(emb, p_Atf);
  transpose_pack_kernel<<<dim3(N_QKV / 32, Cq / 32), dim3(32, 8)>>>(w_qkv, p_wqkvT, N_QKV);
  transpose_pack_kernel<<<dim3(Cq / 32, Cq / 32), dim3(32, 8)>>>(w_proj, p_wprojT, Cq);

  tc_gemm_kernel<0><<<dim3(N_QKV / 128, Mq / 128), 256, GK_SMEM>>>(
      p_Atf, p_wqkvT, b_qkv, nullptr);

  flash_attn_tc_kernel<<<dim3(Bq * Hq, Tq / QT), 128, ATTN_SMEM>>>();

  tc_gemm_kernel<1><<<dim3(Cq / 128, Mq / 128), 256, GK_SMEM>>>(
      p_Y, p_wprojT, b_proj, out);
}

// round 10
// speedup vs baseline: 5.9088x; 1.1809x over previous
#include <cuda_runtime.h>
#include <cuda_bf16.h>
#include <cstdint>

// Problem constants
#define Bq 32
#define Tq 576
#define Cq 1024
#define Hq 16
#define Dq 64
#define Mq (Bq * Tq)          // 18432
#define N_QKV (3 * Cq)        // 3072

// Scratch (device globals; no allocation allowed)
__device__ float g_Q[(size_t)Bq * Hq * Tq * Dq];   // [B,H,T,D], tf32-rounded
__device__ float g_K[(size_t)Bq * Hq * Tq * Dq];
__device__ float g_V[(size_t)Bq * Hq * Tq * Dq];
__device__ float g_Y[(size_t)Mq * Cq];             // attention out, PACKED-A layout
__device__ float g_Atf[(size_t)Mq * Cq];           // emb tf32, PACKED-A layout
__device__ float g_WqkvT[(size_t)N_QKV * Cq];      // PACKED-B layout
__device__ float g_WprojT[(size_t)Cq * Cq];        // PACKED-B layout

// ---------------------------------------------------------------------------
// Fragment-packed layouts (K = 1024 -> 32 k-blocks of 32); see round 9.
// packA float4 view: Af4[(mblk*32+kblk)*1024 + ((m16)*4+ks)*32 + lid]
// packB float2 view: Bf2[(nblk*32+kblk)*2048 + (nt*4+ks)*32 + lid]
// ---------------------------------------------------------------------------
__device__ __forceinline__ size_t packA_idx(int m, int k) {
  const int mblk = m >> 7, kblk = k >> 5;
  const int mt = (m >> 4) & 7, ks = (k >> 3) & 3;
  const int g = m & 7, mh = (m >> 3) & 1;
  const int tig = k & 3, kh = (k >> 2) & 1;
  return ((((size_t)(mblk * 32 + kblk) * 8 + mt) * 4 + ks) * 32 + (g * 4 + tig)) * 4
         + (mh + 2 * kh);
}

__device__ __forceinline__ size_t packB_idx(int n, int k) {
  const int nblk = n >> 7, kblk = k >> 5;
  const int nt = (n >> 3) & 15, ks = (k >> 3) & 3;
  const int g = n & 7;
  const int tig = k & 3, kh = (k >> 2) & 1;
  return ((((size_t)(nblk * 32 + kblk) * 16 + nt) * 4 + ks) * 32 + (g * 4 + tig)) * 2
         + kh;
}

// ---------------------------------------------------------------------------
__device__ __forceinline__ float f2tf32(float x) {
  uint32_t r;
  asm("cvt.rna.tf32.f32 %0, %1;" : "=r"(r) : "f"(x));
  return __uint_as_float(r);
}

__device__ __forceinline__ void cp_async16(uint32_t saddr, const void* gaddr) {
  asm volatile("cp.async.cg.shared.global [%0], [%1], 16;" :: "r"(saddr), "l"(gaddr));
}
#define CP_COMMIT() asm volatile("cp.async.commit_group;" ::: "memory")
#define CP_WAIT(n)  asm volatile("cp.async.wait_group %0;" :: "n"(n) : "memory")

__device__ __forceinline__ uint32_t smem_u32(const void* p) {
  uint32_t a;
  asm("{ .reg .u64 t; cvta.to.shared.u64 t, %1; cvt.u32.u64 %0, t; }"
      : "=r"(a) : "l"(p));
  return a;
}

__device__ __forceinline__ void mma_tf32(float* c, const uint32_t* a, const uint32_t* b) {
  asm volatile(
      "mma.sync.aligned.m16n8k8.row.col.f32.tf32.tf32.f32 "
      "{%0,%1,%2,%3}, {%4,%5,%6,%7}, {%8,%9}, {%0,%1,%2,%3};"
      : "+f"(c[0]), "+f"(c[1]), "+f"(c[2]), "+f"(c[3])
      : "r"(a[0]), "r"(a[1]), "r"(a[2]), "r"(a[3]), "r"(b[0]), "r"(b[1]));
}

__device__ __forceinline__ void mma_tf32_2(float* c, const uint32_t* a,
                                           uint32_t b0, uint32_t b1) {
  asm volatile(
      "mma.sync.aligned.m16n8k8.row.col.f32.tf32.tf32.f32 "
      "{%0,%1,%2,%3}, {%4,%5,%6,%7}, {%8,%9}, {%0,%1,%2,%3};"
      : "+f"(c[0]), "+f"(c[1]), "+f"(c[2]), "+f"(c[3])
      : "r"(a[0]), "r"(a[1]), "r"(a[2]), "r"(a[3]), "r"(b0), "r"(b1));
}

// ---------------------------------------------------------------------------
// emb -> tf32-rounded, packed-A layout
// ---------------------------------------------------------------------------
__global__ __launch_bounds__(256) void round_pack_kernel(const float* __restrict__ src,
                                                         float* __restrict__ dst) {
  const int i = blockIdx.x * 256 + threadIdx.x;
  if (i < Mq * Cq / 4) {
    const int m = (i * 4) / Cq;
    const int k = (i * 4) % Cq;
    const float4 v = ((const float4*)src)[i];
    dst[packA_idx(m, k + 0)] = f2tf32(v.x);
    dst[packA_idx(m, k + 1)] = f2tf32(v.y);
    dst[packA_idx(m, k + 2)] = f2tf32(v.z);
    dst[packA_idx(m, k + 3)] = f2tf32(v.w);
  }
}

// ---------------------------------------------------------------------------
// Weight transpose + tf32 + packed-B: dst_packedB[n][k] = tf32(src[k][n])
// ---------------------------------------------------------------------------
__global__ __launch_bounds__(256) void transpose_pack_kernel(
    const float* __restrict__ src, float* __restrict__ dst, int C) {
  __shared__ float t[32][33];
  const int c0 = blockIdx.x * 32, r0 = blockIdx.y * 32;
  const int x = threadIdx.x, y = threadIdx.y;   // 32 x 8
#pragma unroll
  for (int i = 0; i < 32; i += 8)
    t[y + i][x] = src[(size_t)(r0 + y + i) * C + c0 + x];
  __syncthreads();
#pragma unroll
  for (int i = 0; i < 32; i += 8)
    dst[packB_idx(c0 + y + i, r0 + x)] = f2tf32(t[x][y + i]);
}

// ---------------------------------------------------------------------------
// Barrier-free tf32 mma.sync GEMM: fragments streamed straight from global
// (L2/L1) via LDG.NC on the packed layout. No shared memory, no syncthreads.
// CTA 128x128, 8 warps (2m x 4n); per-warp 1-kstep register prefetch.
// MODE 0: QKV scatter epilogue; MODE 1: plain store.
// ---------------------------------------------------------------------------
#define G_NK 32

#define LOADG(kt_, ks_, c_) do {                                               \
    _Pragma("unroll")                                                          \
    for (int mt_ = 0; mt_ < 4; mt_++)                                          \
      af[c_][mt_] = __ldg(Afw + (kt_) * 1024 + (mt_ * 4 + (ks_)) * 32);        \
    _Pragma("unroll")                                                          \
    for (int nt_ = 0; nt_ < 4; nt_++)                                          \
      bf[c_][nt_] = __ldg(Bfw + (kt_) * 2048 + (nt_ * 4 + (ks_)) * 32);        \
  } while (0)

template <int MODE>
__global__ __launch_bounds__(256, 2) void tc_gemm_kernel(
    const float* __restrict__ A, const float* __restrict__ BT,
    const float* __restrict__ bias, float* __restrict__ Out) {
  const int tid = threadIdx.x;
  const int wid = tid >> 5;
  const int lid = tid & 31;
  const int mblk = blockIdx.y;
  const int nblk = blockIdx.x;
  const int m0 = mblk * 128;
  const int n0 = nblk * 128;
  const int warp_m = wid & 1;
  const int warp_n = wid >> 1;
  const int g = lid >> 2, tig = lid & 3;

  // Per-warp fragment base pointers in the packed global arrays.
  const float4* Afw = (const float4*)A + (size_t)mblk * 32768 + warp_m * 512 + lid;
  const float2* Bfw = (const float2*)BT + (size_t)nblk * 65536 + warp_n * 512 + lid;

  float acc[4][4][4];
#pragma unroll
  for (int i = 0; i < 4; i++)
#pragma unroll
    for (int j = 0; j < 4; j++)
#pragma unroll
      for (int q = 0; q < 4; q++) acc[i][j][q] = 0.f;

  float4 af[2][4];
  float2 bf[2][4];

  LOADG(0, 0, 0);
  for (int kt = 0; kt < G_NK; kt++) {
#pragma unroll
    for (int ks = 0; ks < 4; ks++) {
      const int step = kt * 4 + ks;
      const int c = step & 1;
      const int nstep = step + 1;
      if (nstep < G_NK * 4) LOADG(nstep >> 2, nstep & 3, c ^ 1);
#pragma unroll
      for (int mt = 0; mt < 4; mt++)
#pragma unroll
        for (int nt = 0; nt < 4; nt++)
          mma_tf32(acc[mt][nt], (const uint32_t*)&af[c][mt],
                   (const uint32_t*)&bf[c][nt]);
    }
  }

  // Epilogue (same fragment->logical mapping as rounds 4-9)
#pragma unroll
  for (int mt = 0; mt < 4; mt++) {
    const int row0 = m0 + warp_m * 64 + mt * 16 + g;
#pragma unroll
    for (int half = 0; half < 2; half++) {
      const int m = row0 + half * 8;
      const int bb = m / Tq;
      const int t = m % Tq;
#pragma unroll
      for (int nt = 0; nt < 4; nt++) {
        const int n = n0 + warp_n * 32 + nt * 8 + tig * 2;
        const float2 bv = *(const float2*)&bias[n];
        float2 o;
        o.x = acc[mt][nt][half * 2 + 0] + bv.x;
        o.y = acc[mt][nt][half * 2 + 1] + bv.y;
        if (MODE == 0) {
          o.x = f2tf32(o.x);
          o.y = f2tf32(o.y);
          const int which = n >> 10;
          const int ccn = n & 1023;
          const int h = ccn >> 6;
          const int d = ccn & 63;
          float* dst = (which == 0) ? g_Q : (which == 1) ? g_K : g_V;
          *(float2*)(dst + ((size_t)(bb * Hq + h) * Tq + t) * Dq + d) = o;
        } else {
          *(float2*)(Out + (size_t)m * Cq + n) = o;
        }
      }
    }
  }
}

// ---------------------------------------------------------------------------
// Tensor-core causal flash attention (round 5 core; epilogue writes packed-A Y).
// ---------------------------------------------------------------------------
#define QT 64
#define KST 68
#define VST 72
#define PST 68
#define KBUF (64 * KST)
#define VBUF (64 * VST)
#define ATTN_SMEM ((2 * KBUF + 2 * VBUF + 64 * PST) * 4)   // 89088 B

__device__ __forceinline__ void attn_prefetch(const float* Kg, const float* Vg,
                                              float* Ksb, float* Vsb, int tid) {
#pragma unroll
  for (int i = 0; i < 8; i++) {
    const int c = tid + i * 128;
    const int r = c >> 4;
    const int c4 = (c & 15) * 4;
    cp_async16(smem_u32(Ksb + r * KST + c4), Kg + (size_t)r * Dq + c4);
    cp_async16(smem_u32(Vsb + r * VST + c4), Vg + (size_t)r * Dq + c4);
  }
  CP_COMMIT();
}

__global__ __launch_bounds__(128) void flash_attn_tc_kernel() {
  const int bh = blockIdx.x;
  const int qt = blockIdx.y;
  const int b = bh / Hq;
  const int h = bh % Hq;

  const float* Qb = g_Q + (size_t)bh * Tq * Dq;
  const float* Kb = g_K + (size_t)bh * Tq * Dq;
  const float* Vb = g_V + (size_t)bh * Tq * Dq;

  extern __shared__ float smf[];
  float* KsA = smf;
  float* VsA = smf + 2 * KBUF;
  float* Ps  = smf + 2 * KBUF + 2 * VBUF;

  const int tid = threadIdx.x;
  const int wid = tid >> 5;
  const int lid = tid & 31;
  const int g = lid >> 2;
  const int tig = lid & 3;
  const int q0 = qt * QT;
  const int nkt = qt + 1;

  attn_prefetch(Kb, Vb, KsA, VsA, tid);

  {
#pragma unroll
    for (int i = 0; i < 8; i++) {
      const int c = tid + i * 128;
      const int r = c >> 4;
      const int c4 = (c & 15) * 4;
      const float4 v = *(const float4*)&Qb[(size_t)(q0 + r) * Dq + c4];
      float* dr = &Ps[r * PST + c4];
      dr[0] = v.x; dr[1] = v.y; dr[2] = v.z; dr[3] = v.w;
    }
  }
  __syncthreads();

  uint32_t qa[8][4];
  {
    const uint32_t* Qsm = (const uint32_t*)Ps;
    const int r0 = 16 * wid + g;
#pragma unroll
    for (int ks = 0; ks < 8; ks++) {
      const int kb = 8 * ks + tig;
      qa[ks][0] = Qsm[r0 * PST + kb];
      qa[ks][1] = Qsm[(r0 + 8) * PST + kb];
      qa[ks][2] = Qsm[r0 * PST + kb + 4];
      qa[ks][3] = Qsm[(r0 + 8) * PST + kb + 4];
    }
  }

  float o[8][4];
#pragma unroll
  for (int i = 0; i < 8; i++)
#pragma unroll
    for (int j = 0; j < 4; j++) o[i][j] = 0.f;
  float m0r = -1e30f, m1r = -1e30f, l0 = 0.f, l1 = 0.f;
  const float scale = 1.0f / 64.0f;
  const int myrow0 = 16 * wid + g;
  const int myrow1 = myrow0 + 8;

  for (int kt = 0; kt < nkt; kt++) {
    const int buf = kt & 1;
    __syncthreads();
    if (kt + 1 < nkt) {
      attn_prefetch(Kb + (size_t)(kt + 1) * 64 * Dq, Vb + (size_t)(kt + 1) * 64 * Dq,
                    KsA + (buf ^ 1) * KBUF, VsA + (buf ^ 1) * VBUF, tid);
      CP_WAIT(1);
    } else {
      CP_WAIT(0);
    }
    __syncthreads();

    const uint32_t* Ksm = (const uint32_t*)(KsA + buf * KBUF);
    float s[8][4];
#pragma unroll
    for (int nt = 0; nt < 8; nt++) {
      s[nt][0] = s[nt][1] = s[nt][2] = s[nt][3] = 0.f;
      const uint32_t* kr = Ksm + (8 * nt + g) * KST;
#pragma unroll
      for (int ks = 0; ks < 8; ks++) {
        const int kb = 8 * ks + tig;
        mma_tf32_2(s[nt], qa[ks], kr[kb], kr[kb + 4]);
      }
    }

    const bool diag = (kt == qt);
    float mx0 = -1e30f, mx1 = -1e30f;
#pragma unroll
    for (int nt = 0; nt < 8; nt++) {
#pragma unroll
      for (int ccx = 0; ccx < 2; ccx++) {
        const int kcol = 8 * nt + 2 * tig + ccx;
        const bool ok0 = !diag || (kcol <= myrow0);
        const bool ok1 = !diag || (kcol <= myrow1);
        s[nt][ccx]     = ok0 ? s[nt][ccx] * scale     : -1e30f;
        s[nt][2 + ccx] = ok1 ? s[nt][2 + ccx] * scale : -1e30f;
        mx0 = fmaxf(mx0, s[nt][ccx]);
        mx1 = fmaxf(mx1, s[nt][2 + ccx]);
      }
    }
    mx0 = fmaxf(mx0, __shfl_xor_sync(0xffffffffu, mx0, 1));
    mx0 = fmaxf(mx0, __shfl_xor_sync(0xffffffffu, mx0, 2));
    mx1 = fmaxf(mx1, __shfl_xor_sync(0xffffffffu, mx1, 1));
    mx1 = fmaxf(mx1, __shfl_xor_sync(0xffffffffu, mx1, 2));

    const float nm0 = fmaxf(m0r, mx0);
    const float nm1 = fmaxf(m1r, mx1);
    const float c0 = __expf(m0r - nm0);
    const float c1 = __expf(m1r - nm1);

    float ps0 = 0.f, ps1 = 0.f;
#pragma unroll
    for (int nt = 0; nt < 8; nt++) {
      const float p00 = __expf(s[nt][0] - nm0);
      const float p01 = __expf(s[nt][1] - nm0);
      const float p10 = __expf(s[nt][2] - nm1);
      const float p11 = __expf(s[nt][3] - nm1);
      ps0 += p00 + p01;
      ps1 += p10 + p11;
      float2 w0 = {f2tf32(p00), f2tf32(p01)};
      float2 w1 = {f2tf32(p10), f2tf32(p11)};
      *(float2*)&Ps[myrow0 * PST + 8 * nt + 2 * tig] = w0;
      *(float2*)&Ps[myrow1 * PST + 8 * nt + 2 * tig] = w1;
    }
    ps0 += __shfl_xor_sync(0xffffffffu, ps0, 1);
    ps0 += __shfl_xor_sync(0xffffffffu, ps0, 2);
    ps1 += __shfl_xor_sync(0xffffffffu, ps1, 1);
    ps1 += __shfl_xor_sync(0xffffffffu, ps1, 2);
    l0 = l0 * c0 + ps0;
    l1 = l1 * c1 + ps1;
    m0r = nm0;
    m1r = nm1;
#pragma unroll
    for (int dt = 0; dt < 8; dt++) {
      o[dt][0] *= c0; o[dt][1] *= c0;
      o[dt][2] *= c1; o[dt][3] *= c1;
    }
    __syncwarp();

    const uint32_t* Psm = (const uint32_t*)Ps;
    const uint32_t* Vsm = (const uint32_t*)(VsA + buf * VBUF);
    uint32_t pa[8][4];
#pragma unroll
    for (int ks = 0; ks < 8; ks++) {
      const int kb = 8 * ks + tig;
      pa[ks][0] = Psm[myrow0 * PST + kb];
      pa[ks][1] = Psm[myrow1 * PST + kb];
      pa[ks][2] = Psm[myrow0 * PST + kb + 4];
      pa[ks][3] = Psm[myrow1 * PST + kb + 4];
    }
#pragma unroll
    for (int dt = 0; dt < 8; dt++) {
#pragma unroll
      for (int ks = 0; ks < 8; ks++) {
        const uint32_t b0 = Vsm[(8 * ks + tig) * VST + 8 * dt + g];
        const uint32_t b1 = Vsm[(8 * ks + tig + 4) * VST + 8 * dt + g];
        mma_tf32_2(o[dt], pa[ks], b0, b1);
      }
    }
  }

  // finalize: write Y in packed-A layout (global row = b*Tq + q, col = h*64+d)
  const float inv0 = 1.0f / l0;
  const float inv1 = 1.0f / l1;
  const int mr0 = b * Tq + q0 + myrow0;
  const int mr1 = b * Tq + q0 + myrow1;
#pragma unroll
  for (int dt = 0; dt < 8; dt++) {
    const int kc = h * 64 + 8 * dt + 2 * tig;
    g_Y[packA_idx(mr0, kc)]     = f2tf32(o[dt][0] * inv0);
    g_Y[packA_idx(mr0, kc + 1)] = f2tf32(o[dt][1] * inv0);
    g_Y[packA_idx(mr1, kc)]     = f2tf32(o[dt][2] * inv1);
    g_Y[packA_idx(mr1, kc + 1)] = f2tf32(o[dt][3] * inv1);
  }
}

// ---------------------------------------------------------------------------
extern "C" void kernel_launch(void* const* d_in, const int* in_sizes, int n_in,
                              void* d_out, int out_size) {
  const float* emb    = (const float*)d_in[0];
  const float* w_qkv  = (const float*)d_in[1];
  const float* b_qkv  = (const float*)d_in[2];
  const float* w_proj = (const float*)d_in[3];
  const float* b_proj = (const float*)d_in[4];
  float* out = (float*)d_out;

  static float* p_wqkvT = nullptr;
  static float* p_wprojT = nullptr;
  static float* p_Y = nullptr;
  static float* p_Atf = nullptr;
  static bool init_done = false;
  if (!init_done) {
    cudaGetSymbolAddress((void**)&p_wqkvT, g_WqkvT);
    cudaGetSymbolAddress((void**)&p_wprojT, g_WprojT);
    cudaGetSymbolAddress((void**)&p_Y, g_Y);
    cudaGetSymbolAddress((void**)&p_Atf, g_Atf);
    cudaFuncSetAttribute(flash_attn_tc_kernel,
                         cudaFuncAttributeMaxDynamicSharedMemorySize, ATTN_SMEM);
    init_done = true;
  }

  round_pack_kernel<<<Mq * Cq / 4 / 256, 256>>>(emb, p_Atf);
  transpose_pack_kernel<<<dim3(N_QKV / 32, Cq / 32), dim3(32, 8)>>>(w_qkv, p_wqkvT, N_QKV);
  transpose_pack_kernel<<<dim3(Cq / 32, Cq / 32), dim3(32, 8)>>>(w_proj, p_wprojT, Cq);

  tc_gemm_kernel<0><<<dim3(N_QKV / 128, Mq / 128), 256>>>(
      p_Atf, p_wqkvT, b_qkv, nullptr);

  flash_attn_tc_kernel<<<dim3(Bq * Hq, Tq / QT), 128, ATTN_SMEM>>>();

  tc_gemm_kernel<1><<<dim3(Cq / 128, Mq / 128), 256>>>(
      p_Y, p_wprojT, b_proj, out);
}

// round 11
// speedup vs baseline: 6.3112x; 1.0681x over previous
#include <cuda_runtime.h>
#include <cuda_bf16.h>
#include <cstdint>

// Problem constants
#define Bq 32
#define Tq 576
#define Cq 1024
#define Hq 16
#define Dq 64
#define Mq (Bq * Tq)          // 18432
#define N_QKV (3 * Cq)        // 3072

// Scratch (device globals; no allocation allowed)
__device__ float g_Q[(size_t)Bq * Hq * Tq * Dq];   // [B,H,T,D], tf32-rounded
__device__ float g_K[(size_t)Bq * Hq * Tq * Dq];
__device__ float g_V[(size_t)Bq * Hq * Tq * Dq];
__device__ float g_Y[(size_t)Mq * Cq];             // attention out, PACKED-A layout
__device__ float g_Atf[(size_t)Mq * Cq];           // emb tf32, PACKED-A layout
__device__ float g_WqkvT[(size_t)N_QKV * Cq];      // PACKED-B layout
__device__ float g_WprojT[(size_t)Cq * Cq];        // PACKED-B layout

// ---------------------------------------------------------------------------
// Fragment-packed layouts (K = 1024 -> 32 k-blocks of 32); see round 9.
// packA float4 view: Af4[(mblk*32+kblk)*1024 + ((m16)*4+ks)*32 + lid]
// packB float2 view: Bf2[(nblk*32+kblk)*2048 + (nt*4+ks)*32 + lid]
// ---------------------------------------------------------------------------
__device__ __forceinline__ size_t packA_idx(int m, int k) {
  const int mblk = m >> 7, kblk = k >> 5;
  const int mt = (m >> 4) & 7, ks = (k >> 3) & 3;
  const int g = m & 7, mh = (m >> 3) & 1;
  const int tig = k & 3, kh = (k >> 2) & 1;
  return ((((size_t)(mblk * 32 + kblk) * 8 + mt) * 4 + ks) * 32 + (g * 4 + tig)) * 4
         + (mh + 2 * kh);
}

__device__ __forceinline__ size_t packB_idx(int n, int k) {
  const int nblk = n >> 7, kblk = k >> 5;
  const int nt = (n >> 3) & 15, ks = (k >> 3) & 3;
  const int g = n & 7;
  const int tig = k & 3, kh = (k >> 2) & 1;
  return ((((size_t)(nblk * 32 + kblk) * 16 + nt) * 4 + ks) * 32 + (g * 4 + tig)) * 2
         + kh;
}

// ---------------------------------------------------------------------------
__device__ __forceinline__ float f2tf32(float x) {
  uint32_t r;
  asm("cvt.rna.tf32.f32 %0, %1;" : "=r"(r) : "f"(x));
  return __uint_as_float(r);
}

__device__ __forceinline__ void cp_async16(uint32_t saddr, const void* gaddr) {
  asm volatile("cp.async.cg.shared.global [%0], [%1], 16;" :: "r"(saddr), "l"(gaddr));
}
#define CP_COMMIT() asm volatile("cp.async.commit_group;" ::: "memory")
#define CP_WAIT(n)  asm volatile("cp.async.wait_group %0;" :: "n"(n) : "memory")

__device__ __forceinline__ uint32_t smem_u32(const void* p) {
  uint32_t a;
  asm("{ .reg .u64 t; cvta.to.shared.u64 t, %1; cvt.u32.u64 %0, t; }"
      : "=r"(a) : "l"(p));
  return a;
}

__device__ __forceinline__ void prefetch_l1(const void* p) {
  asm volatile("prefetch.global.L1 [%0];" :: "l"(p));
}

__device__ __forceinline__ void mma_tf32(float* c, const uint32_t* a, const uint32_t* b) {
  asm volatile(
      "mma.sync.aligned.m16n8k8.row.col.f32.tf32.tf32.f32 "
      "{%0,%1,%2,%3}, {%4,%5,%6,%7}, {%8,%9}, {%0,%1,%2,%3};"
      : "+f"(c[0]), "+f"(c[1]), "+f"(c[2]), "+f"(c[3])
      : "r"(a[0]), "r"(a[1]), "r"(a[2]), "r"(a[3]), "r"(b[0]), "r"(b[1]));
}

__device__ __forceinline__ void mma_tf32_2(float* c, const uint32_t* a,
                                           uint32_t b0, uint32_t b1) {
  asm volatile(
      "mma.sync.aligned.m16n8k8.row.col.f32.tf32.tf32.f32 "
      "{%0,%1,%2,%3}, {%4,%5,%6,%7}, {%8,%9}, {%0,%1,%2,%3};"
      : "+f"(c[0]), "+f"(c[1]), "+f"(c[2]), "+f"(c[3])
      : "r"(a[0]), "r"(a[1]), "r"(a[2]), "r"(a[3]), "r"(b0), "r"(b1));
}

// ---------------------------------------------------------------------------
// emb -> tf32-rounded, packed-A layout
// ---------------------------------------------------------------------------
__global__ __launch_bounds__(256) void round_pack_kernel(const float* __restrict__ src,
                                                         float* __restrict__ dst) {
  const int i = blockIdx.x * 256 + threadIdx.x;
  if (i < Mq * Cq / 4) {
    const int m = (i * 4) / Cq;
    const int k = (i * 4) % Cq;
    const float4 v = ((const float4*)src)[i];
    dst[packA_idx(m, k + 0)] = f2tf32(v.x);
    dst[packA_idx(m, k + 1)] = f2tf32(v.y);
    dst[packA_idx(m, k + 2)] = f2tf32(v.z);
    dst[packA_idx(m, k + 3)] = f2tf32(v.w);
  }
}

// ---------------------------------------------------------------------------
// Weight transpose + tf32 + packed-B: dst_packedB[n][k] = tf32(src[k][n])
// ---------------------------------------------------------------------------
__global__ __launch_bounds__(256) void transpose_pack_kernel(
    const float* __restrict__ src, float* __restrict__ dst, int C) {
  __shared__ float t[32][33];
  const int c0 = blockIdx.x * 32, r0 = blockIdx.y * 32;
  const int x = threadIdx.x, y = threadIdx.y;   // 32 x 8
#pragma unroll
  for (int i = 0; i < 32; i += 8)
    t[y + i][x] = src[(size_t)(r0 + y + i) * C + c0 + x];
  __syncthreads();
#pragma unroll
  for (int i = 0; i < 32; i += 8)
    dst[packB_idx(c0 + y + i, r0 + x)] = f2tf32(t[x][y + i]);
}

// ---------------------------------------------------------------------------
// Barrier-free tf32 mma.sync GEMM: fragments streamed from global via __ldg
// on the packed layout; register prefetch depth 1 + L1 prefetch depth 2.
// CTA 128x128, 8 warps (2m x 4n). MODE 0: QKV scatter; MODE 1: plain store.
// ---------------------------------------------------------------------------
#define G_NK 32

#define LOADG(kt_, ks_, c_) do {                                               \
    _Pragma("unroll")                                                          \
    for (int mt_ = 0; mt_ < 4; mt_++)                                          \
      af[c_][mt_] = __ldg(Afw + (kt_) * 1024 + (mt_ * 4 + (ks_)) * 32);        \
    _Pragma("unroll")                                                          \
    for (int nt_ = 0; nt_ < 4; nt_++)                                          \
      bf[c_][nt_] = __ldg(Bfw + (kt_) * 2048 + (nt_ * 4 + (ks_)) * 32);        \
  } while (0)

#define PREFG(kt_, ks_) do {                                                   \
    _Pragma("unroll")                                                          \
    for (int mt_ = 0; mt_ < 4; mt_++)                                          \
      prefetch_l1(Afw + (kt_) * 1024 + (mt_ * 4 + (ks_)) * 32);                \
    _Pragma("unroll")                                                          \
    for (int nt_ = 0; nt_ < 4; nt_++)                                          \
      prefetch_l1(Bfw + (kt_) * 2048 + (nt_ * 4 + (ks_)) * 32);                \
  } while (0)

template <int MODE>
__global__ __launch_bounds__(256, 2) void tc_gemm_kernel(
    const float* __restrict__ A, const float* __restrict__ BT,
    const float* __restrict__ bias, float* __restrict__ Out) {
  const int tid = threadIdx.x;
  const int wid = tid >> 5;
  const int lid = tid & 31;
  const int mblk = blockIdx.y;
  const int nblk = blockIdx.x;
  const int m0 = mblk * 128;
  const int n0 = nblk * 128;
  const int warp_m = wid & 1;
  const int warp_n = wid >> 1;
  const int g = lid >> 2, tig = lid & 3;

  // Per-warp fragment base pointers in the packed global arrays.
  const float4* Afw = (const float4*)A + (size_t)mblk * 32768 + warp_m * 512 + lid;
  const float2* Bfw = (const float2*)BT + (size_t)nblk * 65536 + warp_n * 512 + lid;

  float acc[4][4][4];
#pragma unroll
  for (int i = 0; i < 4; i++)
#pragma unroll
    for (int j = 0; j < 4; j++)
#pragma unroll
      for (int q = 0; q < 4; q++) acc[i][j][q] = 0.f;

  float4 af[2][4];
  float2 bf[2][4];

  LOADG(0, 0, 0);
  PREFG(0, 1);
  for (int kt = 0; kt < G_NK; kt++) {
#pragma unroll
    for (int ks = 0; ks < 4; ks++) {
      const int step = kt * 4 + ks;
      const int c = step & 1;
      const int nstep = step + 1;
      if (nstep < G_NK * 4) LOADG(nstep >> 2, nstep & 3, c ^ 1);
      const int pstep = step + 2;
      if (pstep < G_NK * 4) PREFG(pstep >> 2, pstep & 3);
#pragma unroll
      for (int mt = 0; mt < 4; mt++)
#pragma unroll
        for (int nt = 0; nt < 4; nt++)
          mma_tf32(acc[mt][nt], (const uint32_t*)&af[c][mt],
                   (const uint32_t*)&bf[c][nt]);
    }
  }

  // Epilogue (same fragment->logical mapping as rounds 4-10)
#pragma unroll
  for (int mt = 0; mt < 4; mt++) {
    const int row0 = m0 + warp_m * 64 + mt * 16 + g;
#pragma unroll
    for (int half = 0; half < 2; half++) {
      const int m = row0 + half * 8;
      const int bb = m / Tq;
      const int t = m % Tq;
#pragma unroll
      for (int nt = 0; nt < 4; nt++) {
        const int n = n0 + warp_n * 32 + nt * 8 + tig * 2;
        const float2 bv = *(const float2*)&bias[n];
        float2 o;
        o.x = acc[mt][nt][half * 2 + 0] + bv.x;
        o.y = acc[mt][nt][half * 2 + 1] + bv.y;
        if (MODE == 0) {
          o.x = f2tf32(o.x);
          o.y = f2tf32(o.y);
          const int which = n >> 10;
          const int ccn = n & 1023;
          const int h = ccn >> 6;
          const int d = ccn & 63;
          float* dst = (which == 0) ? g_Q : (which == 1) ? g_K : g_V;
          *(float2*)(dst + ((size_t)(bb * Hq + h) * Tq + t) * Dq + d) = o;
        } else {
          *(float2*)(Out + (size_t)m * Cq + n) = o;
        }
      }
    }
  }
}

// ---------------------------------------------------------------------------
// Tensor-core causal flash attention (round 5 core; epilogue writes packed-A Y).
// ---------------------------------------------------------------------------
#define QT 64
#define KST 68
#define VST 72
#define PST 68
#define KBUF (64 * KST)
#define VBUF (64 * VST)
#define ATTN_SMEM ((2 * KBUF + 2 * VBUF + 64 * PST) * 4)   // 89088 B

__device__ __forceinline__ void attn_prefetch(const float* Kg, const float* Vg,
                                              float* Ksb, float* Vsb, int tid) {
#pragma unroll
  for (int i = 0; i < 8; i++) {
    const int c = tid + i * 128;
    const int r = c >> 4;
    const int c4 = (c & 15) * 4;
    cp_async16(smem_u32(Ksb + r * KST + c4), Kg + (size_t)r * Dq + c4);
    cp_async16(smem_u32(Vsb + r * VST + c4), Vg + (size_t)r * Dq + c4);
  }
  CP_COMMIT();
}

__global__ __launch_bounds__(128) void flash_attn_tc_kernel() {
  const int bh = blockIdx.x;
  const int qt = blockIdx.y;
  const int b = bh / Hq;
  const int h = bh % Hq;

  const float* Qb = g_Q + (size_t)bh * Tq * Dq;
  const float* Kb = g_K + (size_t)bh * Tq * Dq;
  const float* Vb = g_V + (size_t)bh * Tq * Dq;

  extern __shared__ float smf[];
  float* KsA = smf;
  float* VsA = smf + 2 * KBUF;
  float* Ps  = smf + 2 * KBUF + 2 * VBUF;

  const int tid = threadIdx.x;
  const int wid = tid >> 5;
  const int lid = tid & 31;
  const int g = lid >> 2;
  const int tig = lid & 3;
  const int q0 = qt * QT;
  const int nkt = qt + 1;

  attn_prefetch(Kb, Vb, KsA, VsA, tid);

  {
#pragma unroll
    for (int i = 0; i < 8; i++) {
      const int c = tid + i * 128;
      const int r = c >> 4;
      const int c4 = (c & 15) * 4;
      const float4 v = *(const float4*)&Qb[(size_t)(q0 + r) * Dq + c4];
      float* dr = &Ps[r * PST + c4];
      dr[0] = v.x; dr[1] = v.y; dr[2] = v.z; dr[3] = v.w;
    }
  }
  __syncthreads();

  uint32_t qa[8][4];
  {
    const uint32_t* Qsm = (const uint32_t*)Ps;
    const int r0 = 16 * wid + g;
#pragma unroll
    for (int ks = 0; ks < 8; ks++) {
      const int kb = 8 * ks + tig;
      qa[ks][0] = Qsm[r0 * PST + kb];
      qa[ks][1] = Qsm[(r0 + 8) * PST + kb];
      qa[ks][2] = Qsm[r0 * PST + kb + 4];
      qa[ks][3] = Qsm[(r0 + 8) * PST + kb + 4];
    }
  }

  float o[8][4];
#pragma unroll
  for (int i = 0; i < 8; i++)
#pragma unroll
    for (int j = 0; j < 4; j++) o[i][j] = 0.f;
  float m0r = -1e30f, m1r = -1e30f, l0 = 0.f, l1 = 0.f;
  const float scale = 1.0f / 64.0f;
  const int myrow0 = 16 * wid + g;
  const int myrow1 = myrow0 + 8;

  for (int kt = 0; kt < nkt; kt++) {
    const int buf = kt & 1;
    __syncthreads();
    if (kt + 1 < nkt) {
      attn_prefetch(Kb + (size_t)(kt + 1) * 64 * Dq, Vb + (size_t)(kt + 1) * 64 * Dq,
                    KsA + (buf ^ 1) * KBUF, VsA + (buf ^ 1) * VBUF, tid);
      CP_WAIT(1);
    } else {
      CP_WAIT(0);
    }
    __syncthreads();

    const uint32_t* Ksm = (const uint32_t*)(KsA + buf * KBUF);
    float s[8][4];
#pragma unroll
    for (int nt = 0; nt < 8; nt++) {
      s[nt][0] = s[nt][1] = s[nt][2] = s[nt][3] = 0.f;
      const uint32_t* kr = Ksm + (8 * nt + g) * KST;
#pragma unroll
      for (int ks = 0; ks < 8; ks++) {
        const int kb = 8 * ks + tig;
        mma_tf32_2(s[nt], qa[ks], kr[kb], kr[kb + 4]);
      }
    }

    const bool diag = (kt == qt);
    float mx0 = -1e30f, mx1 = -1e30f;
#pragma unroll
    for (int nt = 0; nt < 8; nt++) {
#pragma unroll
      for (int ccx = 0; ccx < 2; ccx++) {
        const int kcol = 8 * nt + 2 * tig + ccx;
        const bool ok0 = !diag || (kcol <= myrow0);
        const bool ok1 = !diag || (kcol <= myrow1);
        s[nt][ccx]     = ok0 ? s[nt][ccx] * scale     : -1e30f;
        s[nt][2 + ccx] = ok1 ? s[nt][2 + ccx] * scale : -1e30f;
        mx0 = fmaxf(mx0, s[nt][ccx]);
        mx1 = fmaxf(mx1, s[nt][2 + ccx]);
      }
    }
    mx0 = fmaxf(mx0, __shfl_xor_sync(0xffffffffu, mx0, 1));
    mx0 = fmaxf(mx0, __shfl_xor_sync(0xffffffffu, mx0, 2));
    mx1 = fmaxf(mx1, __shfl_xor_sync(0xffffffffu, mx1, 1));
    mx1 = fmaxf(mx1, __shfl_xor_sync(0xffffffffu, mx1, 2));

    const float nm0 = fmaxf(m0r, mx0);
    const float nm1 = fmaxf(m1r, mx1);
    const float c0 = __expf(m0r - nm0);
    const float c1 = __expf(m1r - nm1);

    float ps0 = 0.f, ps1 = 0.f;
#pragma unroll
    for (int nt = 0; nt < 8; nt++) {
      const float p00 = __expf(s[nt][0] - nm0);
      const float p01 = __expf(s[nt][1] - nm0);
      const float p10 = __expf(s[nt][2] - nm1);
      const float p11 = __expf(s[nt][3] - nm1);
      ps0 += p00 + p01;
      ps1 += p10 + p11;
      float2 w0 = {f2tf32(p00), f2tf32(p01)};
      float2 w1 = {f2tf32(p10), f2tf32(p11)};
      *(float2*)&Ps[myrow0 * PST + 8 * nt + 2 * tig] = w0;
      *(float2*)&Ps[myrow1 * PST + 8 * nt + 2 * tig] = w1;
    }
    ps0 += __shfl_xor_sync(0xffffffffu, ps0, 1);
    ps0 += __shfl_xor_sync(0xffffffffu, ps0, 2);
    ps1 += __shfl_xor_sync(0xffffffffu, ps1, 1);
    ps1 += __shfl_xor_sync(0xffffffffu, ps1, 2);
    l0 = l0 * c0 + ps0;
    l1 = l1 * c1 + ps1;
    m0r = nm0;
    m1r = nm1;
#pragma unroll
    for (int dt = 0; dt < 8; dt++) {
      o[dt][0] *= c0; o[dt][1] *= c0;
      o[dt][2] *= c1; o[dt][3] *= c1;
    }
    __syncwarp();

    const uint32_t* Psm = (const uint32_t*)Ps;
    const uint32_t* Vsm = (const uint32_t*)(VsA + buf * VBUF);
    uint32_t pa[8][4];
#pragma unroll
    for (int ks = 0; ks < 8; ks++) {
      const int kb = 8 * ks + tig;
      pa[ks][0] = Psm[myrow0 * PST + kb];
      pa[ks][1] = Psm[myrow1 * PST + kb];
      pa[ks][2] = Psm[myrow0 * PST + kb + 4];
      pa[ks][3] = Psm[myrow1 * PST + kb + 4];
    }
#pragma unroll
    for (int dt = 0; dt < 8; dt++) {
#pragma unroll
      for (int ks = 0; ks < 8; ks++) {
        const uint32_t b0 = Vsm[(8 * ks + tig) * VST + 8 * dt + g];
        const uint32_t b1 = Vsm[(8 * ks + tig + 4) * VST + 8 * dt + g];
        mma_tf32_2(o[dt], pa[ks], b0, b1);
      }
    }
  }

  // finalize: write Y in packed-A layout (global row = b*Tq + q, col = h*64+d)
  const float inv0 = 1.0f / l0;
  const float inv1 = 1.0f / l1;
  const int mr0 = b * Tq + q0 + myrow0;
  const int mr1 = b * Tq + q0 + myrow1;
#pragma unroll
  for (int dt = 0; dt < 8; dt++) {
    const int kc = h * 64 + 8 * dt + 2 * tig;
    g_Y[packA_idx(mr0, kc)]     = f2tf32(o[dt][0] * inv0);
    g_Y[packA_idx(mr0, kc + 1)] = f2tf32(o[dt][1] * inv0);
    g_Y[packA_idx(mr1, kc)]     = f2tf32(o[dt][2] * inv1);
    g_Y[packA_idx(mr1, kc + 1)] = f2tf32(o[dt][3] * inv1);
  }
}

// ---------------------------------------------------------------------------
extern "C" void kernel_launch(void* const* d_in, const int* in_sizes, int n_in,
                              void* d_out, int out_size) {
  const float* emb    = (const float*)d_in[0];
  const float* w_qkv  = (const float*)d_in[1];
  const float* b_qkv  = (const float*)d_in[2];
  const float* w_proj = (const float*)d_in[3];
  const float* b_proj = (const float*)d_in[4];
  float* out = (float*)d_out;

  static float* p_wqkvT = nullptr;
  static float* p_wprojT = nullptr;
  static float* p_Y = nullptr;
  static float* p_Atf = nullptr;
  static bool init_done = false;
  if (!init_done) {
    cudaGetSymbolAddress((void**)&p_wqkvT, g_WqkvT);
    cudaGetSymbolAddress((void**)&p_wprojT, g_WprojT);
    cudaGetSymbolAddress((void**)&p_Y, g_Y);
    cudaGetSymbolAddress((void**)&p_Atf, g_Atf);
    cudaFuncSetAttribute(flash_attn_tc_kernel,
                         cudaFuncAttributeMaxDynamicSharedMemorySize, ATTN_SMEM);
    init_done = true;
  }

  round_pack_kernel<<<Mq * Cq / 4 / 256, 256>>>(emb, p_Atf);
  transpose_pack_kernel<<<dim3(N_QKV / 32, Cq / 32), dim3(32, 8)>>>(w_qkv, p_wqkvT, N_QKV);
  transpose_pack_kernel<<<dim3(Cq / 32, Cq / 32), dim3(32, 8)>>>(w_proj, p_wprojT, Cq);

  tc_gemm_kernel<0><<<dim3(N_QKV / 128, Mq / 128), 256>>>(
      p_Atf, p_wqkvT, b_qkv, nullptr);

  flash_attn_tc_kernel<<<dim3(Bq * Hq, Tq / QT), 128, ATTN_SMEM>>>();

  tc_gemm_kernel<1><<<dim3(Cq / 128, Mq / 128), 256>>>(
      p_Y, p_wprojT, b_proj, out);
}